// round 11
// baseline (speedup 1.0000x reference)
#include <cuda_runtime.h>
#include <cuda_fp16.h>
#include <math.h>
#include <stdint.h>

#define SEQ   1024
#define MEMN  1024
#define TT    2048
#define BATCH 4
#define NH    16
#define DH    64
#define DM    1024
#define BH    (BATCH*NH)   // 64

// ---------------- scratch (device globals, all fp16) ----------------
__device__ __half g_ac[(size_t)BH*SEQ*TT];
__device__ __half g_bd[(size_t)BH*SEQ*TT];

__device__ __half g_c [(size_t)8192*1024];
__device__ __half g_p [(size_t)8192*1024];
__device__ __half g_w [(size_t)4096*1024];
__device__ __half g_wo[(size_t)1024*1024];

__device__ __half g_qu[(size_t)BH*SEQ*DH];
__device__ __half g_qv[(size_t)BH*SEQ*DH];
__device__ __half g_k [(size_t)BH*TT*DH];
__device__ __half g_v [(size_t)BH*TT*DH];
__device__ __half g_r [(size_t)BH*TT*DH];

__device__ __half g_ph[(size_t)BH*SEQ*TT];
__device__ __half g_av[(size_t)SEQ*BATCH*DM];   // layout: [b][i][h*64+d]

// ---------------- helpers ----------------
__device__ __forceinline__ uint32_t smem_u32(const void* p){
    uint32_t a;
    asm("{ .reg .u64 t; cvta.to.shared.u64 t, %1; cvt.u32.u64 %0, t; }" : "=r"(a) : "l"(p));
    return a;
}
__device__ __forceinline__ void cp16(uint32_t s, const void* g){
    asm volatile("cp.async.cg.shared.global [%0], [%1], 16;" :: "r"(s), "l"(g));
}
#define CP_COMMIT() asm volatile("cp.async.commit_group;" ::: "memory")
#define CP_WAIT0()  asm volatile("cp.async.wait_group 0;" ::: "memory")

__device__ __forceinline__ void ldm4(uint32_t* r, uint32_t addr){
    asm volatile("ldmatrix.sync.aligned.m8n8.x4.shared.b16 {%0,%1,%2,%3}, [%4];"
        : "=r"(r[0]), "=r"(r[1]), "=r"(r[2]), "=r"(r[3]) : "r"(addr));
}
__device__ __forceinline__ void ldm4t(uint32_t* r, uint32_t addr){
    asm volatile("ldmatrix.sync.aligned.m8n8.x4.trans.shared.b16 {%0,%1,%2,%3}, [%4];"
        : "=r"(r[0]), "=r"(r[1]), "=r"(r[2]), "=r"(r[3]) : "r"(addr));
}
__device__ __forceinline__ void mma_f16(float* c, const uint32_t* a, uint32_t b0, uint32_t b1){
    asm volatile("mma.sync.aligned.m16n8k16.row.col.f32.f16.f16.f32 "
        "{%0,%1,%2,%3}, {%4,%5,%6,%7}, {%8,%9}, {%0,%1,%2,%3};"
        : "+f"(c[0]), "+f"(c[1]), "+f"(c[2]), "+f"(c[3])
        : "r"(a[0]), "r"(a[1]), "r"(a[2]), "r"(a[3]), "r"(b0), "r"(b1));
}
__device__ __forceinline__ uint4 pack8h(const float* v){
    __half2 a = __floats2half2_rn(v[0], v[1]);
    __half2 b = __floats2half2_rn(v[2], v[3]);
    __half2 c = __floats2half2_rn(v[4], v[5]);
    __half2 d = __floats2half2_rn(v[6], v[7]);
    uint4 r;
    r.x = *(uint32_t*)&a; r.y = *(uint32_t*)&b;
    r.z = *(uint32_t*)&c; r.w = *(uint32_t*)&d;
    return r;
}
__device__ __forceinline__ uint32_t packh2(float a, float b){
    __half2 h = __floats2half2_rn(a, b);
    return *(uint32_t*)&h;
}

__device__ __forceinline__ float warpReduceSum(float v){
    #pragma unroll
    for (int o = 16; o > 0; o >>= 1) v += __shfl_xor_sync(0xffffffffu, v, o);
    return v;
}

// ---------------- kernel 0: fp32 -> fp16 conversion ----------------
__global__ __launch_bounds__(256) void conv_kernel(
    const float* __restrict__ x, const float* __restrict__ mem,
    const float* __restrict__ pos, const float* __restrict__ Wqkv,
    const float* __restrict__ Wrel, const float* __restrict__ Wo)
{
    const size_t u = (size_t)blockIdx.x * 256 + threadIdx.x;
    const float* src;
    __half* dst;
    size_t elem;
    if (u < 2097152) {
        elem = u * 4;
        const size_t row = elem >> 10, col = elem & 1023;
        src = (row < 4096) ? (mem + row*1024 + col) : (x + (row-4096)*1024 + col);
        dst = g_c + elem;
    } else if (u < 4194304) {
        elem = (u - 2097152) * 4;
        src = pos + elem;
        dst = g_p + elem;
    } else if (u < 5242880) {
        elem = (u - 4194304) * 4;
        const size_t row = elem >> 10, col = elem & 1023;
        src = (row < 3072) ? (Wqkv + row*1024 + col) : (Wrel + (row-3072)*1024 + col);
        dst = g_w + elem;
    } else {
        elem = (u - 5242880) * 4;
        src = Wo + elem;
        dst = g_wo + elem;
    }
    float4 v = *(const float4*)src;
    __half2 h01 = __floats2half2_rn(v.x, v.y);
    __half2 h23 = __floats2half2_rn(v.z, v.w);
    *(uint2*)dst = make_uint2(*(uint32_t*)&h01, *(uint32_t*)&h23);
}

// ---------------- kernel 1: fp16 projection GEMM (K-chunk 64) ----------------
#define PJ_BUF   36864
#define PJ_SMEM  73728

__global__ __launch_bounds__(256) void proj_mma_kernel(
    const float* __restrict__ pbu, const float* __restrict__ pbv)
{
    extern __shared__ __align__(128) char smem[];
    const uint32_t sbase = smem_u32(smem);
    const int tid = threadIdx.x, lane = tid & 31, wid = tid >> 5;
    const int bid = blockIdx.x;
    int n0, m0;
    if (bid < 256){ n0 = (bid & 7) * 128; m0 = 4096 + (bid >> 3) * 128; }
    else { const int b2 = bid - 256; n0 = 1024 + (b2 % 24) * 128; m0 = (b2 / 24) * 128; }

    const bool is_rel = (n0 >= 3072);
    const __half* Ap = (is_rel ? g_p : g_c) + (size_t)m0 * 1024;
    const __half* Bp = g_w + (size_t)n0 * 1024;

    const int wm = (wid & 3) * 32;
    const int wn = (wid >> 2) * 64;
    const int lsel = lane & 15;
    const int kof  = (lane < 16) ? 0 : 8;

    float acc[2][8][4];
    #pragma unroll
    for (int mt = 0; mt < 2; mt++)
        #pragma unroll
        for (int nt = 0; nt < 8; nt++)
            #pragma unroll
            for (int q = 0; q < 4; q++) acc[mt][nt][q] = 0.f;

    auto issue = [&](int c, int b){
        const int k0 = c * 64;
        const uint32_t sb = sbase + b * PJ_BUF;
        #pragma unroll
        for (int p = 0; p < 4; p++){
            const int u = p * 256 + tid;
            const int row = u >> 3, seg = u & 7;
            const size_t go = (size_t)row * 1024 + k0 + seg * 8;
            const uint32_t so = row * 144 + seg * 16;
            cp16(sb + so,         Ap + go);
            cp16(sb + 18432 + so, Bp + go);
        }
        CP_COMMIT();
    };

    issue(0, 0);
    for (int c = 0; c < 16; c++){
        CP_WAIT0();
        __syncthreads();
        if (c + 1 < 16) issue(c + 1, (c + 1) & 1);
        const uint32_t sb = sbase + (c & 1) * PJ_BUF;
        #pragma unroll
        for (int kk = 0; kk < 64; kk += 16){
            uint32_t ah[2][4], bh[4][4];
            #pragma unroll
            for (int mt = 0; mt < 2; mt++)
                ldm4(ah[mt], sb + (wm + mt*16 + lsel) * 144 + (kk + kof) * 2);
            #pragma unroll
            for (int g = 0; g < 4; g++)
                ldm4(bh[g], sb + 18432 + (wn + g*16 + lsel) * 144 + (kk + kof) * 2);
            #pragma unroll
            for (int mt = 0; mt < 2; mt++)
                #pragma unroll
                for (int nt = 0; nt < 8; nt++){
                    const int g = nt >> 1, s = nt & 1;
                    mma_f16(acc[mt][nt], ah[mt], bh[g][s], bh[g][s+2]);
                }
        }
    }

    __syncthreads();
    float* stg = (float*)smem;
    const int fr = lane >> 2, fc = (lane & 3) * 2;
    #pragma unroll
    for (int mt = 0; mt < 2; mt++)
        #pragma unroll
        for (int nt = 0; nt < 8; nt++){
            const int col = wn + nt*8 + fc;
            const int row0 = wm + mt*16 + fr;
            stg[row0*132 + col]       = acc[mt][nt][0];
            stg[row0*132 + col + 1]   = acc[mt][nt][1];
            stg[(row0+8)*132 + col]   = acc[mt][nt][2];
            stg[(row0+8)*132 + col+1] = acc[mt][nt][3];
        }
    __syncthreads();

    const int rr = tid >> 1, hf = tid & 1;
    const int m = m0 + rr;
    const int t_ = m >> 2, b_ = m & 3;
    const float* src = stg + rr * 132 + hf * 64;
    const int nbase = n0 + hf * 64;
    const int cat = n0 >> 10;
    if (cat == 0){
        const int i = t_ - MEMN;
        const int h = nbase >> 6;
        const size_t off = (((size_t)(b_*NH + h))*SEQ + i)*DH;
        #pragma unroll
        for (int s = 0; s < 8; s++){
            float qu8[8], qv8[8];
            #pragma unroll
            for (int e = 0; e < 8; e++){
                const float v = src[s*8 + e];
                qu8[e] = v + pbu[nbase + s*8 + e];
                qv8[e] = v + pbv[nbase + s*8 + e];
            }
            *(uint4*)(g_qu + off + s*8) = pack8h(qu8);
            *(uint4*)(g_qv + off + s*8) = pack8h(qv8);
        }
    } else {
        const int nn = nbase - cat*1024;
        const int h = nn >> 6;
        __half* bptr = (cat == 1) ? g_k : (cat == 2) ? g_v : g_r;
        const size_t off = (((size_t)(b_*NH + h))*TT + t_)*DH;
        #pragma unroll
        for (int s = 0; s < 8; s++)
            *(uint4*)(bptr + off + s*8) = pack8h(src + s*8);
    }
}

// ---------------- kernel 2: fp16 score GEMMs, A-persistent 8-j-tile loop ----------------
#define SC_SMEM 90112

__global__ __launch_bounds__(256) void score_mma_kernel(int bh0)
{
    extern __shared__ __align__(128) char smem[];
    const uint32_t sbase = smem_u32(smem);
    const int tid = threadIdx.x, lane = tid & 31, wid = tid >> 5;
    const int z = blockIdx.z;
    const int bh = bh0 + (z >> 1), which = z & 1;
    const __half* Ap = (which ? g_qv : g_qu) + (size_t)bh * SEQ * DH;
    const __half* Bp = (which ? g_r  : g_k ) + (size_t)bh * TT  * DH;
    __half* Ob = (which ? g_bd : g_ac) + (size_t)bh * SEQ * TT;
    const int i0 = blockIdx.y * 128;
    const int jg = blockIdx.x * 8;

    const int wm = (wid & 3) * 32;
    const int wn = (wid >> 2) * 64;
    const int lsel = lane & 15;
    const int kof  = (lane < 16) ? 0 : 8;

    auto issueB = [&](int jt, int b){
        const int j0 = (jg + jt) * 128;
        const uint32_t sb = sbase + 18432 + b * 18432;
        #pragma unroll
        for (int p = 0; p < 4; p++){
            const int u = p * 256 + tid;
            const int row = u >> 3, seg = u & 7;
            cp16(sb + row * 144 + seg * 16, Bp + (size_t)(j0 + row) * DH + seg * 8);
        }
        CP_COMMIT();
    };

    {
        #pragma unroll
        for (int p = 0; p < 4; p++){
            const int u = p * 256 + tid;
            const int row = u >> 3, seg = u & 7;
            cp16(sbase + row * 144 + seg * 16, Ap + (size_t)(i0 + row) * DH + seg * 8);
        }
        issueB(0, 0);
    }

    __half* stg = (__half*)(smem + 55296);

    for (int jt = 0; jt < 8; jt++){
        float acc[2][8][4];
        #pragma unroll
        for (int mt = 0; mt < 2; mt++)
            #pragma unroll
            for (int nt = 0; nt < 8; nt++)
                #pragma unroll
                for (int q = 0; q < 4; q++) acc[mt][nt][q] = 0.f;

        CP_WAIT0();
        __syncthreads();
        if (jt + 1 < 8) issueB(jt + 1, (jt + 1) & 1);
        const uint32_t sbB = sbase + 18432 + (jt & 1) * 18432;

        #pragma unroll
        for (int kk = 0; kk < 64; kk += 16){
            uint32_t ah[2][4], bh[4][4];
            #pragma unroll
            for (int mt = 0; mt < 2; mt++)
                ldm4(ah[mt], sbase + (wm + mt*16 + lsel) * 144 + (kk + kof) * 2);
            #pragma unroll
            for (int g = 0; g < 4; g++)
                ldm4(bh[g], sbB + (wn + g*16 + lsel) * 144 + (kk + kof) * 2);
            #pragma unroll
            for (int mt = 0; mt < 2; mt++)
                #pragma unroll
                for (int nt = 0; nt < 8; nt++){
                    const int g = nt >> 1, s = nt & 1;
                    mma_f16(acc[mt][nt], ah[mt], bh[g][s], bh[g][s+2]);
                }
        }

        __syncthreads();
        const int fr = lane >> 2, fc = (lane & 3) * 2;
        #pragma unroll
        for (int mt = 0; mt < 2; mt++)
            #pragma unroll
            for (int nt = 0; nt < 8; nt++){
                const int col = wn + nt*8 + fc;
                const int row0 = wm + mt*16 + fr;
                *(uint32_t*)(stg + row0*136 + col)     = packh2(acc[mt][nt][0], acc[mt][nt][1]);
                *(uint32_t*)(stg + (row0+8)*136 + col) = packh2(acc[mt][nt][2], acc[mt][nt][3]);
            }
        __syncthreads();
        const int rr = tid >> 1, hf = tid & 1;
        const __half* srcp = stg + rr * 136 + hf * 64;
        __half* orow = Ob + (size_t)(i0 + rr) * TT + (jg + jt) * 128 + hf * 64;
        #pragma unroll
        for (int s = 0; s < 8; s++)
            *(uint4*)(orow + s*8) = *(const uint4*)(srcp + s*8);
        __syncthreads();
    }
}

// ---------------- kernel 3: rel-shift + softmax (no max; scores bounded) ----------------
__global__ __launch_bounds__(256) void softmax_shift_kernel(int bh0)
{
    const int i  = blockIdx.x;
    const int bh = bh0 + blockIdx.y;
    const int t  = threadIdx.x;
    const size_t rowoff = ((size_t)bh*SEQ + i) * TT;
    const __half* ac = g_ac + rowoff;
    const __half* bd0 = g_bd + rowoff;
    const __half* bd1 = bd0 + TT;

    float sv[8];
    float lsum = 0.f;
    #pragma unroll
    for (int q = 0; q < 8; q++){
        const int j = q*256 + t;
        const int delta = j - i;
        float bd;
        if (delta <= 1024)      bd = __half2float(bd0[delta + 1023]);
        else if (delta == 1025) bd = 0.f;
        else                    bd = __half2float(bd1[delta - 1026]);
        const float s = (__half2float(ac[j]) + bd) * 0.125f;
        const float p = __expf(s);
        sv[q] = p;
        lsum += p;
    }
    __shared__ float sh[8];
    float wsum = warpReduceSum(lsum);
    if ((t & 31) == 0) sh[t >> 5] = wsum;
    __syncthreads();
    float sum = 0.f;
    #pragma unroll
    for (int w = 0; w < 8; w++) sum += sh[w];
    const float sinv = 1.f / sum;

    __half* ph = g_ph + rowoff;
    #pragma unroll
    for (int q = 0; q < 8; q++){
        const int j = q*256 + t;
        ph[j] = __float2half_rn(sv[q] * sinv);
    }
}

// ---------------- kernel 4: fp16 PV GEMM (K-chunk 64), writes g_av[b][i][..] ----------------
#define PV_BUF   27648
#define PV_SMEM  55296

__global__ __launch_bounds__(256) void pv_mma_kernel(int bh0)
{
    extern __shared__ __align__(128) char smem[];
    const uint32_t sbase = smem_u32(smem);
    const int tid = threadIdx.x, lane = tid & 31, wid = tid >> 5;
    const int bh = bh0 + blockIdx.y;
    const int i0 = blockIdx.x * 128;
    const __half* Pp = g_ph + (size_t)bh*SEQ*TT + (size_t)i0*TT;
    const __half* Vp = g_v + (size_t)bh*TT*DH;

    const int wm = (wid & 3) * 32;
    const int wn = (wid >> 2) * 32;
    const int lsel = lane & 15;
    const int kof  = (lane < 16) ? 0 : 8;
    const int tcol = (lane >> 4) * 8;

    float acc[2][4][4];
    #pragma unroll
    for (int mt = 0; mt < 2; mt++)
        #pragma unroll
        for (int nt = 0; nt < 4; nt++)
            #pragma unroll
            for (int q = 0; q < 4; q++) acc[mt][nt][q] = 0.f;

    auto issue = [&](int c, int b){
        const int k0 = c * 64;
        const uint32_t sb = sbase + b * PV_BUF;
        #pragma unroll
        for (int p = 0; p < 4; p++){
            const int u = p * 256 + tid;
            const int row = u >> 3, seg = u & 7;
            cp16(sb + row * 144 + seg * 16, Pp + (size_t)row * TT + k0 + seg * 8);
        }
        #pragma unroll
        for (int p = 0; p < 2; p++){
            const int u = p * 256 + tid;
            const int row = u >> 3, seg = u & 7;
            cp16(sb + 18432 + row * 144 + seg * 16, Vp + (size_t)(k0 + row) * DH + seg * 8);
        }
        CP_COMMIT();
    };

    issue(0, 0);
    for (int c = 0; c < 32; c++){
        CP_WAIT0();
        __syncthreads();
        if (c + 1 < 32) issue(c + 1, (c + 1) & 1);
        const uint32_t sb = sbase + (c & 1) * PV_BUF;
        #pragma unroll
        for (int kk = 0; kk < 64; kk += 16){
            uint32_t ph[2][4], vh[2][4];
            #pragma unroll
            for (int mt = 0; mt < 2; mt++)
                ldm4(ph[mt], sb + (wm + mt*16 + lsel) * 144 + (kk + kof) * 2);
            #pragma unroll
            for (int g = 0; g < 2; g++)
                ldm4t(vh[g], sb + 18432 + (kk + lsel) * 144 + (wn + g*16 + tcol) * 2);
            #pragma unroll
            for (int mt = 0; mt < 2; mt++)
                #pragma unroll
                for (int nt = 0; nt < 4; nt++){
                    const int g = nt >> 1, s = nt & 1;
                    mma_f16(acc[mt][nt], ph[mt], vh[g][2*s], vh[g][2*s+1]);
                }
        }
    }

    __syncthreads();
    float* stg = (float*)smem;
    const int fr = lane >> 2, fc = (lane & 3) * 2;
    #pragma unroll
    for (int mt = 0; mt < 2; mt++)
        #pragma unroll
        for (int nt = 0; nt < 4; nt++){
            const int col = wn + nt*8 + fc;
            const int row0 = wm + mt*16 + fr;
            stg[row0*68 + col]       = acc[mt][nt][0];
            stg[row0*68 + col + 1]   = acc[mt][nt][1];
            stg[(row0+8)*68 + col]   = acc[mt][nt][2];
            stg[(row0+8)*68 + col+1] = acc[mt][nt][3];
        }
    __syncthreads();
    const int rr = tid >> 1, hf = tid & 1;
    const int b = bh >> 4, h = bh & 15;
    const int i = i0 + rr;
    const float* src = stg + rr * 68 + hf * 32;
    const size_t off = ((size_t)b*SEQ + i)*DM + h*DH + hf*32;   // [b][i][..]
    #pragma unroll
    for (int s = 0; s < 4; s++)
        *(uint4*)(g_av + off + s*8) = pack8h(src + s*8);
}

// ---------------- kernel 5: fp16 out projection + residual (per batch) ----------------
#define OP_BUF   36864
#define OP_SMEM  73728

__global__ __launch_bounds__(256) void outproj_mma_kernel(const float* __restrict__ x,
                                                          float* __restrict__ out, int b)
{
    extern __shared__ __align__(128) char smem[];
    const uint32_t sbase = smem_u32(smem);
    const int tid = threadIdx.x, lane = tid & 31, wid = tid >> 5;
    const int n0 = blockIdx.x * 128;
    const int m0 = blockIdx.y * 128;               // i-range within batch b
    const __half* Ap = g_av + ((size_t)b*SEQ + m0) * 1024;
    const __half* Bp = g_wo + (size_t)n0 * 1024;

    const int wm = (wid & 3) * 32;
    const int wn = (wid >> 2) * 64;
    const int lsel = lane & 15;
    const int kof  = (lane < 16) ? 0 : 8;

    float acc[2][8][4];
    #pragma unroll
    for (int mt = 0; mt < 2; mt++)
        #pragma unroll
        for (int nt = 0; nt < 8; nt++)
            #pragma unroll
            for (int q = 0; q < 4; q++) acc[mt][nt][q] = 0.f;

    auto issue = [&](int c, int bb){
        const int k0 = c * 64;
        const uint32_t sb = sbase + bb * OP_BUF;
        #pragma unroll
        for (int p = 0; p < 4; p++){
            const int u = p * 256 + tid;
            const int row = u >> 3, seg = u & 7;
            const size_t go = (size_t)row * 1024 + k0 + seg * 8;
            const uint32_t so = row * 144 + seg * 16;
            cp16(sb + so,         Ap + go);
            cp16(sb + 18432 + so, Bp + go);
        }
        CP_COMMIT();
    };

    issue(0, 0);
    for (int c = 0; c < 16; c++){
        CP_WAIT0();
        __syncthreads();
        if (c + 1 < 16) issue(c + 1, (c + 1) & 1);
        const uint32_t sb = sbase + (c & 1) * OP_BUF;
        #pragma unroll
        for (int kk = 0; kk < 64; kk += 16){
            uint32_t ah[2][4], bh[4][4];
            #pragma unroll
            for (int mt = 0; mt < 2; mt++)
                ldm4(ah[mt], sb + (wm + mt*16 + lsel) * 144 + (kk + kof) * 2);
            #pragma unroll
            for (int g = 0; g < 4; g++)
                ldm4(bh[g], sb + 18432 + (wn + g*16 + lsel) * 144 + (kk + kof) * 2);
            #pragma unroll
            for (int mt = 0; mt < 2; mt++)
                #pragma unroll
                for (int nt = 0; nt < 8; nt++){
                    const int g = nt >> 1, s = nt & 1;
                    mma_f16(acc[mt][nt], ah[mt], bh[g][s], bh[g][s+2]);
                }
        }
    }

    __syncthreads();
    float* stg = (float*)smem;
    const int fr = lane >> 2, fc = (lane & 3) * 2;
    #pragma unroll
    for (int mt = 0; mt < 2; mt++)
        #pragma unroll
        for (int nt = 0; nt < 8; nt++){
            const int col = wn + nt*8 + fc;
            const int row0 = wm + mt*16 + fr;
            stg[row0*132 + col]       = acc[mt][nt][0];
            stg[row0*132 + col + 1]   = acc[mt][nt][1];
            stg[(row0+8)*132 + col]   = acc[mt][nt][2];
            stg[(row0+8)*132 + col+1] = acc[mt][nt][3];
        }
    __syncthreads();
    const int rr = tid >> 1, hf = tid & 1;
    const int gm = (m0 + rr) * BATCH + b;          // global out row i*4+b
    const float* src = stg + rr * 132 + hf * 64;
    const float* xr = x + (size_t)gm*DM + n0 + hf*64;
    float* orow = out + (size_t)gm*DM + n0 + hf*64;
    #pragma unroll
    for (int s = 0; s < 16; s++){
        float4 v = *(const float4*)(src + s*4);
        float4 xx = *(const float4*)(xr + s*4);
        *(float4*)(orow + s*4) = make_float4(v.x+xx.x, v.y+xx.y, v.z+xx.z, v.w+xx.w);
    }
}

// ---------------- kernel 6: LayerNorm (per batch) ----------------
__global__ __launch_bounds__(256) void ln_kernel(float* __restrict__ out,
                                                 const float* __restrict__ gamma,
                                                 const float* __restrict__ beta, int b)
{
    const int row = blockIdx.x * BATCH + b;
    float* y = out + (size_t)row * DM;
    const int t = threadIdx.x;
    float v[4];
    float s = 0.f, sq = 0.f;
    #pragma unroll
    for (int q = 0; q < 4; q++){
        v[q] = y[q*256 + t];
        s += v[q];
        sq += v[q]*v[q];
    }
    __shared__ float sh[16];
    float ws = warpReduceSum(s);
    float wq = warpReduceSum(sq);
    if ((t & 31) == 0){ sh[t>>5] = ws; sh[8 + (t>>5)] = wq; }
    __syncthreads();
    s = 0.f; sq = 0.f;
    #pragma unroll
    for (int w = 0; w < 8; w++){ s += sh[w]; sq += sh[8+w]; }
    const float mu = s * (1.f/1024.f);
    const float var = sq * (1.f/1024.f) - mu*mu;
    const float rstd = rsqrtf(var + 1e-5f);
    #pragma unroll
    for (int q = 0; q < 4; q++){
        const int d = q*256 + t;
        y[d] = gamma[d] * ((v[q] - mu) * rstd) + beta[d];
    }
}

// ---------------- launch: per-batch pipelined schedule ----------------
#define NCHUNK 4
#define CHBH   16

extern "C" void kernel_launch(void* const* d_in, const int* in_sizes, int n_in,
                              void* d_out, int out_size)
{
    const float* x     = (const float*)d_in[0];
    const float* mem   = (const float*)d_in[1];
    const float* pos   = (const float*)d_in[2];
    const float* pbu   = (const float*)d_in[3];
    const float* pbv   = (const float*)d_in[4];
    const float* Wqkv  = (const float*)d_in[5];
    const float* Wrel  = (const float*)d_in[6];
    const float* Wo    = (const float*)d_in[7];
    const float* gamma = (const float*)d_in[8];
    const float* beta  = (const float*)d_in[9];
    float* out = (float*)d_out;

    static cudaStream_t s1 = nullptr, s2 = nullptr;
    static cudaEvent_t evS[NCHUNK], evM[NCHUNK], evO[NCHUNK];
    if (!s1){
        cudaStreamCreateWithFlags(&s1, cudaStreamNonBlocking);
        cudaStreamCreateWithFlags(&s2, cudaStreamNonBlocking);
        for (int c = 0; c < NCHUNK; c++){
            cudaEventCreateWithFlags(&evS[c], cudaEventDisableTiming);
            cudaEventCreateWithFlags(&evM[c], cudaEventDisableTiming);
            cudaEventCreateWithFlags(&evO[c], cudaEventDisableTiming);
        }
        cudaFuncSetAttribute(proj_mma_kernel,    cudaFuncAttributeMaxDynamicSharedMemorySize, PJ_SMEM);
        cudaFuncSetAttribute(score_mma_kernel,   cudaFuncAttributeMaxDynamicSharedMemorySize, SC_SMEM);
        cudaFuncSetAttribute(pv_mma_kernel,      cudaFuncAttributeMaxDynamicSharedMemorySize, PV_SMEM);
        cudaFuncSetAttribute(outproj_mma_kernel, cudaFuncAttributeMaxDynamicSharedMemorySize, OP_SMEM);
    }

    conv_kernel<<<21504, 256>>>(x, mem, pos, Wqkv, Wrel, Wo);
    proj_mma_kernel<<<1792, 256, PJ_SMEM>>>(pbu, pbv);

    // pipeline: score_c (s0) -> softmax_c (s1) -> pv_c -> outproj_c -> ln_c (s2)
    for (int c = 0; c < NCHUNK; c++){
        score_mma_kernel<<<dim3(2, 8, 2*CHBH), 256, SC_SMEM>>>(c * CHBH);
        cudaEventRecord(evS[c], 0);
        cudaStreamWaitEvent(s1, evS[c], 0);
        softmax_shift_kernel<<<dim3(1024, CHBH), 256, 0, s1>>>(c * CHBH);
        cudaEventRecord(evM[c], s1);

        cudaStreamWaitEvent(s2, evM[c], 0);
        pv_mma_kernel<<<dim3(8, CHBH), 256, PV_SMEM, s2>>>(c * CHBH);
        outproj_mma_kernel<<<dim3(8, 8), 256, OP_SMEM, s2>>>(x, out, c);
        ln_kernel<<<dim3(1024), 256, 0, s2>>>(out, gamma, beta, c);
        cudaEventRecord(evO[c], s2);
    }
    for (int c = 0; c < NCHUNK; c++)
        cudaStreamWaitEvent(0, evO[c], 0);
}

// round 12
// speedup vs baseline: 1.0373x; 1.0373x over previous
#include <cuda_runtime.h>
#include <cuda_fp16.h>
#include <math.h>
#include <stdint.h>

#define SEQ   1024
#define MEMN  1024
#define TT    2048
#define BATCH 4
#define NH    16
#define DH    64
#define DM    1024
#define BH    (BATCH*NH)   // 64

// ---------------- scratch (device globals, all fp16) ----------------
__device__ __half g_ac[(size_t)BH*SEQ*TT];
__device__ __half g_bd[(size_t)BH*SEQ*TT];

__device__ __half g_c [(size_t)8192*1024];
__device__ __half g_p [(size_t)8192*1024];
__device__ __half g_w [(size_t)4096*1024];
__device__ __half g_wo[(size_t)1024*1024];

__device__ __half g_qu[(size_t)BH*SEQ*DH];
__device__ __half g_qv[(size_t)BH*SEQ*DH];
__device__ __half g_k [(size_t)BH*TT*DH];
__device__ __half g_v [(size_t)BH*TT*DH];
__device__ __half g_r [(size_t)BH*TT*DH];

__device__ __half g_ph[(size_t)BH*SEQ*TT];
__device__ __half g_av[(size_t)SEQ*BATCH*DM];   // layout: [b][i][h*64+d]

// ---------------- helpers ----------------
__device__ __forceinline__ uint32_t smem_u32(const void* p){
    uint32_t a;
    asm("{ .reg .u64 t; cvta.to.shared.u64 t, %1; cvt.u32.u64 %0, t; }" : "=r"(a) : "l"(p));
    return a;
}
__device__ __forceinline__ void cp16(uint32_t s, const void* g){
    asm volatile("cp.async.cg.shared.global [%0], [%1], 16;" :: "r"(s), "l"(g));
}
#define CP_COMMIT() asm volatile("cp.async.commit_group;" ::: "memory")
#define CP_WAIT0()  asm volatile("cp.async.wait_group 0;" ::: "memory")

__device__ __forceinline__ void ldm4(uint32_t* r, uint32_t addr){
    asm volatile("ldmatrix.sync.aligned.m8n8.x4.shared.b16 {%0,%1,%2,%3}, [%4];"
        : "=r"(r[0]), "=r"(r[1]), "=r"(r[2]), "=r"(r[3]) : "r"(addr));
}
__device__ __forceinline__ void ldm4t(uint32_t* r, uint32_t addr){
    asm volatile("ldmatrix.sync.aligned.m8n8.x4.trans.shared.b16 {%0,%1,%2,%3}, [%4];"
        : "=r"(r[0]), "=r"(r[1]), "=r"(r[2]), "=r"(r[3]) : "r"(addr));
}
__device__ __forceinline__ void mma_f16(float* c, const uint32_t* a, uint32_t b0, uint32_t b1){
    asm volatile("mma.sync.aligned.m16n8k16.row.col.f32.f16.f16.f32 "
        "{%0,%1,%2,%3}, {%4,%5,%6,%7}, {%8,%9}, {%0,%1,%2,%3};"
        : "+f"(c[0]), "+f"(c[1]), "+f"(c[2]), "+f"(c[3])
        : "r"(a[0]), "r"(a[1]), "r"(a[2]), "r"(a[3]), "r"(b0), "r"(b1));
}
__device__ __forceinline__ uint4 pack8h(const float* v){
    __half2 a = __floats2half2_rn(v[0], v[1]);
    __half2 b = __floats2half2_rn(v[2], v[3]);
    __half2 c = __floats2half2_rn(v[4], v[5]);
    __half2 d = __floats2half2_rn(v[6], v[7]);
    uint4 r;
    r.x = *(uint32_t*)&a; r.y = *(uint32_t*)&b;
    r.z = *(uint32_t*)&c; r.w = *(uint32_t*)&d;
    return r;
}
__device__ __forceinline__ uint32_t packh2(float a, float b){
    __half2 h = __floats2half2_rn(a, b);
    return *(uint32_t*)&h;
}

__device__ __forceinline__ float warpReduceSum(float v){
    #pragma unroll
    for (int o = 16; o > 0; o >>= 1) v += __shfl_xor_sync(0xffffffffu, v, o);
    return v;
}

// ---------------- kernel 0: fp32 -> fp16 conversion ----------------
__global__ __launch_bounds__(256) void conv_kernel(
    const float* __restrict__ x, const float* __restrict__ mem,
    const float* __restrict__ pos, const float* __restrict__ Wqkv,
    const float* __restrict__ Wrel, const float* __restrict__ Wo)
{
    const size_t u = (size_t)blockIdx.x * 256 + threadIdx.x;
    const float* src;
    __half* dst;
    size_t elem;
    if (u < 2097152) {
        elem = u * 4;
        const size_t row = elem >> 10, col = elem & 1023;
        src = (row < 4096) ? (mem + row*1024 + col) : (x + (row-4096)*1024 + col);
        dst = g_c + elem;
    } else if (u < 4194304) {
        elem = (u - 2097152) * 4;
        src = pos + elem;
        dst = g_p + elem;
    } else if (u < 5242880) {
        elem = (u - 4194304) * 4;
        const size_t row = elem >> 10, col = elem & 1023;
        src = (row < 3072) ? (Wqkv + row*1024 + col) : (Wrel + (row-3072)*1024 + col);
        dst = g_w + elem;
    } else {
        elem = (u - 5242880) * 4;
        src = Wo + elem;
        dst = g_wo + elem;
    }
    float4 v = *(const float4*)src;
    __half2 h01 = __floats2half2_rn(v.x, v.y);
    __half2 h23 = __floats2half2_rn(v.z, v.w);
    *(uint2*)dst = make_uint2(*(uint32_t*)&h01, *(uint32_t*)&h23);
}

// ---------------- kernel 1: fp16 projection GEMM (K-chunk 64) ----------------
#define PJ_BUF   36864
#define PJ_SMEM  73728

__global__ __launch_bounds__(256) void proj_mma_kernel(
    const float* __restrict__ pbu, const float* __restrict__ pbv)
{
    extern __shared__ __align__(128) char smem[];
    const uint32_t sbase = smem_u32(smem);
    const int tid = threadIdx.x, lane = tid & 31, wid = tid >> 5;
    const int bid = blockIdx.x;
    int n0, m0;
    if (bid < 256){ n0 = (bid & 7) * 128; m0 = 4096 + (bid >> 3) * 128; }
    else { const int b2 = bid - 256; n0 = 1024 + (b2 % 24) * 128; m0 = (b2 / 24) * 128; }

    const bool is_rel = (n0 >= 3072);
    const __half* Ap = (is_rel ? g_p : g_c) + (size_t)m0 * 1024;
    const __half* Bp = g_w + (size_t)n0 * 1024;

    const int wm = (wid & 3) * 32;
    const int wn = (wid >> 2) * 64;
    const int lsel = lane & 15;
    const int kof  = (lane < 16) ? 0 : 8;

    float acc[2][8][4];
    #pragma unroll
    for (int mt = 0; mt < 2; mt++)
        #pragma unroll
        for (int nt = 0; nt < 8; nt++)
            #pragma unroll
            for (int q = 0; q < 4; q++) acc[mt][nt][q] = 0.f;

    auto issue = [&](int c, int b){
        const int k0 = c * 64;
        const uint32_t sb = sbase + b * PJ_BUF;
        #pragma unroll
        for (int p = 0; p < 4; p++){
            const int u = p * 256 + tid;
            const int row = u >> 3, seg = u & 7;
            const size_t go = (size_t)row * 1024 + k0 + seg * 8;
            const uint32_t so = row * 144 + seg * 16;
            cp16(sb + so,         Ap + go);
            cp16(sb + 18432 + so, Bp + go);
        }
        CP_COMMIT();
    };

    issue(0, 0);
    for (int c = 0; c < 16; c++){
        CP_WAIT0();
        __syncthreads();
        if (c + 1 < 16) issue(c + 1, (c + 1) & 1);
        const uint32_t sb = sbase + (c & 1) * PJ_BUF;
        #pragma unroll
        for (int kk = 0; kk < 64; kk += 16){
            uint32_t ah[2][4], bh[4][4];
            #pragma unroll
            for (int mt = 0; mt < 2; mt++)
                ldm4(ah[mt], sb + (wm + mt*16 + lsel) * 144 + (kk + kof) * 2);
            #pragma unroll
            for (int g = 0; g < 4; g++)
                ldm4(bh[g], sb + 18432 + (wn + g*16 + lsel) * 144 + (kk + kof) * 2);
            #pragma unroll
            for (int mt = 0; mt < 2; mt++)
                #pragma unroll
                for (int nt = 0; nt < 8; nt++){
                    const int g = nt >> 1, s = nt & 1;
                    mma_f16(acc[mt][nt], ah[mt], bh[g][s], bh[g][s+2]);
                }
        }
    }

    __syncthreads();
    float* stg = (float*)smem;
    const int fr = lane >> 2, fc = (lane & 3) * 2;
    #pragma unroll
    for (int mt = 0; mt < 2; mt++)
        #pragma unroll
        for (int nt = 0; nt < 8; nt++){
            const int col = wn + nt*8 + fc;
            const int row0 = wm + mt*16 + fr;
            stg[row0*132 + col]       = acc[mt][nt][0];
            stg[row0*132 + col + 1]   = acc[mt][nt][1];
            stg[(row0+8)*132 + col]   = acc[mt][nt][2];
            stg[(row0+8)*132 + col+1] = acc[mt][nt][3];
        }
    __syncthreads();

    const int rr = tid >> 1, hf = tid & 1;
    const int m = m0 + rr;
    const int t_ = m >> 2, b_ = m & 3;
    const float* src = stg + rr * 132 + hf * 64;
    const int nbase = n0 + hf * 64;
    const int cat = n0 >> 10;
    if (cat == 0){
        const int i = t_ - MEMN;
        const int h = nbase >> 6;
        const size_t off = (((size_t)(b_*NH + h))*SEQ + i)*DH;
        #pragma unroll
        for (int s = 0; s < 8; s++){
            float qu8[8], qv8[8];
            #pragma unroll
            for (int e = 0; e < 8; e++){
                const float v = src[s*8 + e];
                qu8[e] = v + pbu[nbase + s*8 + e];
                qv8[e] = v + pbv[nbase + s*8 + e];
            }
            *(uint4*)(g_qu + off + s*8) = pack8h(qu8);
            *(uint4*)(g_qv + off + s*8) = pack8h(qv8);
        }
    } else {
        const int nn = nbase - cat*1024;
        const int h = nn >> 6;
        __half* bptr = (cat == 1) ? g_k : (cat == 2) ? g_v : g_r;
        const size_t off = (((size_t)(b_*NH + h))*TT + t_)*DH;
        #pragma unroll
        for (int s = 0; s < 8; s++)
            *(uint4*)(bptr + off + s*8) = pack8h(src + s*8);
    }
}

// ---------------- kernel 2: fp16 score GEMMs, A-persistent 8-j-tile loop ----------------
#define SC_SMEM 90112

__global__ __launch_bounds__(256) void score_mma_kernel(int bh0)
{
    extern __shared__ __align__(128) char smem[];
    const uint32_t sbase = smem_u32(smem);
    const int tid = threadIdx.x, lane = tid & 31, wid = tid >> 5;
    const int z = blockIdx.z;
    const int bh = bh0 + (z >> 1), which = z & 1;
    const __half* Ap = (which ? g_qv : g_qu) + (size_t)bh * SEQ * DH;
    const __half* Bp = (which ? g_r  : g_k ) + (size_t)bh * TT  * DH;
    __half* Ob = (which ? g_bd : g_ac) + (size_t)bh * SEQ * TT;
    const int i0 = blockIdx.y * 128;
    const int jg = blockIdx.x * 8;

    const int wm = (wid & 3) * 32;
    const int wn = (wid >> 2) * 64;
    const int lsel = lane & 15;
    const int kof  = (lane < 16) ? 0 : 8;

    auto issueB = [&](int jt, int b){
        const int j0 = (jg + jt) * 128;
        const uint32_t sb = sbase + 18432 + b * 18432;
        #pragma unroll
        for (int p = 0; p < 4; p++){
            const int u = p * 256 + tid;
            const int row = u >> 3, seg = u & 7;
            cp16(sb + row * 144 + seg * 16, Bp + (size_t)(j0 + row) * DH + seg * 8);
        }
        CP_COMMIT();
    };

    {
        #pragma unroll
        for (int p = 0; p < 4; p++){
            const int u = p * 256 + tid;
            const int row = u >> 3, seg = u & 7;
            cp16(sbase + row * 144 + seg * 16, Ap + (size_t)(i0 + row) * DH + seg * 8);
        }
        issueB(0, 0);
    }

    __half* stg = (__half*)(smem + 55296);

    for (int jt = 0; jt < 8; jt++){
        float acc[2][8][4];
        #pragma unroll
        for (int mt = 0; mt < 2; mt++)
            #pragma unroll
            for (int nt = 0; nt < 8; nt++)
                #pragma unroll
                for (int q = 0; q < 4; q++) acc[mt][nt][q] = 0.f;

        CP_WAIT0();
        __syncthreads();
        if (jt + 1 < 8) issueB(jt + 1, (jt + 1) & 1);
        const uint32_t sbB = sbase + 18432 + (jt & 1) * 18432;

        #pragma unroll
        for (int kk = 0; kk < 64; kk += 16){
            uint32_t ah[2][4], bh[4][4];
            #pragma unroll
            for (int mt = 0; mt < 2; mt++)
                ldm4(ah[mt], sbase + (wm + mt*16 + lsel) * 144 + (kk + kof) * 2);
            #pragma unroll
            for (int g = 0; g < 4; g++)
                ldm4(bh[g], sbB + (wn + g*16 + lsel) * 144 + (kk + kof) * 2);
            #pragma unroll
            for (int mt = 0; mt < 2; mt++)
                #pragma unroll
                for (int nt = 0; nt < 8; nt++){
                    const int g = nt >> 1, s = nt & 1;
                    mma_f16(acc[mt][nt], ah[mt], bh[g][s], bh[g][s+2]);
                }
        }

        __syncthreads();
        const int fr = lane >> 2, fc = (lane & 3) * 2;
        #pragma unroll
        for (int mt = 0; mt < 2; mt++)
            #pragma unroll
            for (int nt = 0; nt < 8; nt++){
                const int col = wn + nt*8 + fc;
                const int row0 = wm + mt*16 + fr;
                *(uint32_t*)(stg + row0*136 + col)     = packh2(acc[mt][nt][0], acc[mt][nt][1]);
                *(uint32_t*)(stg + (row0+8)*136 + col) = packh2(acc[mt][nt][2], acc[mt][nt][3]);
            }
        __syncthreads();
        const int rr = tid >> 1, hf = tid & 1;
        const __half* srcp = stg + rr * 136 + hf * 64;
        __half* orow = Ob + (size_t)(i0 + rr) * TT + (jg + jt) * 128 + hf * 64;
        #pragma unroll
        for (int s = 0; s < 8; s++)
            *(uint4*)(orow + s*8) = *(const uint4*)(srcp + s*8);
        __syncthreads();
    }
}

// ---------------- kernel 3: rel-shift + softmax (no max; scores bounded) ----------------
__global__ __launch_bounds__(256) void softmax_shift_kernel(int bh0)
{
    const int i  = blockIdx.x;
    const int bh = bh0 + blockIdx.y;
    const int t  = threadIdx.x;
    const size_t rowoff = ((size_t)bh*SEQ + i) * TT;
    const __half* ac = g_ac + rowoff;
    const __half* bd0 = g_bd + rowoff;
    const __half* bd1 = bd0 + TT;

    float sv[8];
    float lsum = 0.f;
    #pragma unroll
    for (int q = 0; q < 8; q++){
        const int j = q*256 + t;
        const int delta = j - i;
        float bd;
        if (delta <= 1024)      bd = __half2float(bd0[delta + 1023]);
        else if (delta == 1025) bd = 0.f;
        else                    bd = __half2float(bd1[delta - 1026]);
        const float s = (__half2float(ac[j]) + bd) * 0.125f;
        const float p = __expf(s);
        sv[q] = p;
        lsum += p;
    }
    __shared__ float sh[8];
    float wsum = warpReduceSum(lsum);
    if ((t & 31) == 0) sh[t >> 5] = wsum;
    __syncthreads();
    float sum = 0.f;
    #pragma unroll
    for (int w = 0; w < 8; w++) sum += sh[w];
    const float sinv = 1.f / sum;

    __half* ph = g_ph + rowoff;
    #pragma unroll
    for (int q = 0; q < 8; q++){
        const int j = q*256 + t;
        ph[j] = __float2half_rn(sv[q] * sinv);
    }
}

// ---------------- kernel 4: fp16 PV GEMM (K-chunk 64), writes g_av[b][i][..] ----------------
#define PV_BUF   27648
#define PV_SMEM  55296

__global__ __launch_bounds__(256) void pv_mma_kernel(int bh0)
{
    extern __shared__ __align__(128) char smem[];
    const uint32_t sbase = smem_u32(smem);
    const int tid = threadIdx.x, lane = tid & 31, wid = tid >> 5;
    const int bh = bh0 + blockIdx.y;
    const int i0 = blockIdx.x * 128;
    const __half* Pp = g_ph + (size_t)bh*SEQ*TT + (size_t)i0*TT;
    const __half* Vp = g_v + (size_t)bh*TT*DH;

    const int wm = (wid & 3) * 32;
    const int wn = (wid >> 2) * 32;
    const int lsel = lane & 15;
    const int kof  = (lane < 16) ? 0 : 8;
    const int tcol = (lane >> 4) * 8;

    float acc[2][4][4];
    #pragma unroll
    for (int mt = 0; mt < 2; mt++)
        #pragma unroll
        for (int nt = 0; nt < 4; nt++)
            #pragma unroll
            for (int q = 0; q < 4; q++) acc[mt][nt][q] = 0.f;

    auto issue = [&](int c, int b){
        const int k0 = c * 64;
        const uint32_t sb = sbase + b * PV_BUF;
        #pragma unroll
        for (int p = 0; p < 4; p++){
            const int u = p * 256 + tid;
            const int row = u >> 3, seg = u & 7;
            cp16(sb + row * 144 + seg * 16, Pp + (size_t)row * TT + k0 + seg * 8);
        }
        #pragma unroll
        for (int p = 0; p < 2; p++){
            const int u = p * 256 + tid;
            const int row = u >> 3, seg = u & 7;
            cp16(sb + 18432 + row * 144 + seg * 16, Vp + (size_t)(k0 + row) * DH + seg * 8);
        }
        CP_COMMIT();
    };

    issue(0, 0);
    for (int c = 0; c < 32; c++){
        CP_WAIT0();
        __syncthreads();
        if (c + 1 < 32) issue(c + 1, (c + 1) & 1);
        const uint32_t sb = sbase + (c & 1) * PV_BUF;
        #pragma unroll
        for (int kk = 0; kk < 64; kk += 16){
            uint32_t ph[2][4], vh[2][4];
            #pragma unroll
            for (int mt = 0; mt < 2; mt++)
                ldm4(ph[mt], sb + (wm + mt*16 + lsel) * 144 + (kk + kof) * 2);
            #pragma unroll
            for (int g = 0; g < 2; g++)
                ldm4t(vh[g], sb + 18432 + (kk + lsel) * 144 + (wn + g*16 + tcol) * 2);
            #pragma unroll
            for (int mt = 0; mt < 2; mt++)
                #pragma unroll
                for (int nt = 0; nt < 4; nt++){
                    const int g = nt >> 1, s = nt & 1;
                    mma_f16(acc[mt][nt], ph[mt], vh[g][2*s], vh[g][2*s+1]);
                }
        }
    }

    __syncthreads();
    float* stg = (float*)smem;
    const int fr = lane >> 2, fc = (lane & 3) * 2;
    #pragma unroll
    for (int mt = 0; mt < 2; mt++)
        #pragma unroll
        for (int nt = 0; nt < 4; nt++){
            const int col = wn + nt*8 + fc;
            const int row0 = wm + mt*16 + fr;
            stg[row0*68 + col]       = acc[mt][nt][0];
            stg[row0*68 + col + 1]   = acc[mt][nt][1];
            stg[(row0+8)*68 + col]   = acc[mt][nt][2];
            stg[(row0+8)*68 + col+1] = acc[mt][nt][3];
        }
    __syncthreads();
    const int rr = tid >> 1, hf = tid & 1;
    const int b = bh >> 4, h = bh & 15;
    const int i = i0 + rr;
    const float* src = stg + rr * 68 + hf * 32;
    const size_t off = ((size_t)b*SEQ + i)*DM + h*DH + hf*32;   // [b][i][..]
    #pragma unroll
    for (int s = 0; s < 4; s++)
        *(uint4*)(g_av + off + s*8) = pack8h(src + s*8);
}

// ---------------- kernel 5: fp16 out projection + residual (batch range) ----------------
#define OP_BUF   36864
#define OP_SMEM  73728

__global__ __launch_bounds__(256) void outproj_mma_kernel(const float* __restrict__ x,
                                                          float* __restrict__ out, int b0)
{
    extern __shared__ __align__(128) char smem[];
    const uint32_t sbase = smem_u32(smem);
    const int tid = threadIdx.x, lane = tid & 31, wid = tid >> 5;
    const int n0 = blockIdx.x * 128;
    const int b  = b0 + (blockIdx.y >> 3);
    const int m0 = (blockIdx.y & 7) * 128;         // i-range within batch b
    const __half* Ap = g_av + ((size_t)b*SEQ + m0) * 1024;
    const __half* Bp = g_wo + (size_t)n0 * 1024;

    const int wm = (wid & 3) * 32;
    const int wn = (wid >> 2) * 64;
    const int lsel = lane & 15;
    const int kof  = (lane < 16) ? 0 : 8;

    float acc[2][8][4];
    #pragma unroll
    for (int mt = 0; mt < 2; mt++)
        #pragma unroll
        for (int nt = 0; nt < 8; nt++)
            #pragma unroll
            for (int q = 0; q < 4; q++) acc[mt][nt][q] = 0.f;

    auto issue = [&](int c, int bb){
        const int k0 = c * 64;
        const uint32_t sb = sbase + bb * OP_BUF;
        #pragma unroll
        for (int p = 0; p < 4; p++){
            const int u = p * 256 + tid;
            const int row = u >> 3, seg = u & 7;
            const size_t go = (size_t)row * 1024 + k0 + seg * 8;
            const uint32_t so = row * 144 + seg * 16;
            cp16(sb + so,         Ap + go);
            cp16(sb + 18432 + so, Bp + go);
        }
        CP_COMMIT();
    };

    issue(0, 0);
    for (int c = 0; c < 16; c++){
        CP_WAIT0();
        __syncthreads();
        if (c + 1 < 16) issue(c + 1, (c + 1) & 1);
        const uint32_t sb = sbase + (c & 1) * OP_BUF;
        #pragma unroll
        for (int kk = 0; kk < 64; kk += 16){
            uint32_t ah[2][4], bh[4][4];
            #pragma unroll
            for (int mt = 0; mt < 2; mt++)
                ldm4(ah[mt], sb + (wm + mt*16 + lsel) * 144 + (kk + kof) * 2);
            #pragma unroll
            for (int g = 0; g < 4; g++)
                ldm4(bh[g], sb + 18432 + (wn + g*16 + lsel) * 144 + (kk + kof) * 2);
            #pragma unroll
            for (int mt = 0; mt < 2; mt++)
                #pragma unroll
                for (int nt = 0; nt < 8; nt++){
                    const int g = nt >> 1, s = nt & 1;
                    mma_f16(acc[mt][nt], ah[mt], bh[g][s], bh[g][s+2]);
                }
        }
    }

    __syncthreads();
    float* stg = (float*)smem;
    const int fr = lane >> 2, fc = (lane & 3) * 2;
    #pragma unroll
    for (int mt = 0; mt < 2; mt++)
        #pragma unroll
        for (int nt = 0; nt < 8; nt++){
            const int col = wn + nt*8 + fc;
            const int row0 = wm + mt*16 + fr;
            stg[row0*132 + col]       = acc[mt][nt][0];
            stg[row0*132 + col + 1]   = acc[mt][nt][1];
            stg[(row0+8)*132 + col]   = acc[mt][nt][2];
            stg[(row0+8)*132 + col+1] = acc[mt][nt][3];
        }
    __syncthreads();
    const int rr = tid >> 1, hf = tid & 1;
    const int gm = (m0 + rr) * BATCH + b;          // global out row i*4+b
    const float* src = stg + rr * 132 + hf * 64;
    const float* xr = x + (size_t)gm*DM + n0 + hf*64;
    float* orow = out + (size_t)gm*DM + n0 + hf*64;
    #pragma unroll
    for (int s = 0; s < 16; s++){
        float4 v = *(const float4*)(src + s*4);
        float4 xx = *(const float4*)(xr + s*4);
        *(float4*)(orow + s*4) = make_float4(v.x+xx.x, v.y+xx.y, v.z+xx.z, v.w+xx.w);
    }
}

// ---------------- kernel 6: LayerNorm (all rows) ----------------
__global__ __launch_bounds__(256) void ln_kernel(float* __restrict__ out,
                                                 const float* __restrict__ gamma,
                                                 const float* __restrict__ beta)
{
    const int row = blockIdx.x;
    float* y = out + (size_t)row * DM;
    const int t = threadIdx.x;
    float v[4];
    float s = 0.f, sq = 0.f;
    #pragma unroll
    for (int q = 0; q < 4; q++){
        v[q] = y[q*256 + t];
        s += v[q];
        sq += v[q]*v[q];
    }
    __shared__ float sh[16];
    float ws = warpReduceSum(s);
    float wq = warpReduceSum(sq);
    if ((t & 31) == 0){ sh[t>>5] = ws; sh[8 + (t>>5)] = wq; }
    __syncthreads();
    s = 0.f; sq = 0.f;
    #pragma unroll
    for (int w = 0; w < 8; w++){ s += sh[w]; sq += sh[8+w]; }
    const float mu = s * (1.f/1024.f);
    const float var = sq * (1.f/1024.f) - mu*mu;
    const float rstd = rsqrtf(var + 1e-5f);
    #pragma unroll
    for (int q = 0; q < 4; q++){
        const int d = q*256 + t;
        y[d] = gamma[d] * ((v[q] - mu) * rstd) + beta[d];
    }
}

// ---------------- launch: R9 schedule + independent pvB/outprojB chain ----------------
#define NCHUNK 4
#define CHBH   16

extern "C" void kernel_launch(void* const* d_in, const int* in_sizes, int n_in,
                              void* d_out, int out_size)
{
    const float* x     = (const float*)d_in[0];
    const float* mem   = (const float*)d_in[1];
    const float* pos   = (const float*)d_in[2];
    const float* pbu   = (const float*)d_in[3];
    const float* pbv   = (const float*)d_in[4];
    const float* Wqkv  = (const float*)d_in[5];
    const float* Wrel  = (const float*)d_in[6];
    const float* Wo    = (const float*)d_in[7];
    const float* gamma = (const float*)d_in[8];
    const float* beta  = (const float*)d_in[9];
    float* out = (float*)d_out;

    static cudaStream_t s1 = nullptr, s2 = nullptr;
    static cudaEvent_t evS[NCHUNK], evM[NCHUNK], evB;
    if (!s1){
        cudaStreamCreateWithFlags(&s1, cudaStreamNonBlocking);
        cudaStreamCreateWithFlags(&s2, cudaStreamNonBlocking);
        for (int c = 0; c < NCHUNK; c++){
            cudaEventCreateWithFlags(&evS[c], cudaEventDisableTiming);
            cudaEventCreateWithFlags(&evM[c], cudaEventDisableTiming);
        }
        cudaEventCreateWithFlags(&evB, cudaEventDisableTiming);
        cudaFuncSetAttribute(proj_mma_kernel,    cudaFuncAttributeMaxDynamicSharedMemorySize, PJ_SMEM);
        cudaFuncSetAttribute(score_mma_kernel,   cudaFuncAttributeMaxDynamicSharedMemorySize, SC_SMEM);
        cudaFuncSetAttribute(pv_mma_kernel,      cudaFuncAttributeMaxDynamicSharedMemorySize, PV_SMEM);
        cudaFuncSetAttribute(outproj_mma_kernel, cudaFuncAttributeMaxDynamicSharedMemorySize, OP_SMEM);
    }

    conv_kernel<<<21504, 256>>>(x, mem, pos, Wqkv, Wrel, Wo);
    proj_mma_kernel<<<1792, 256, PJ_SMEM>>>(pbu, pbv);

    // score chunks on stream 0; softmax chunks on s1
    for (int c = 0; c < NCHUNK; c++){
        score_mma_kernel<<<dim3(2, 8, 2*CHBH), 256, SC_SMEM>>>(c * CHBH);
        cudaEventRecord(evS[c], 0);
        cudaStreamWaitEvent(s1, evS[c], 0);
        softmax_shift_kernel<<<dim3(1024, CHBH), 256, 0, s1>>>(c * CHBH);
        cudaEventRecord(evM[c], s1);
    }

    // chain A on stream 0: pvA (bh 0..47, batches 0-2) -> outprojA (b 0-2)
    cudaStreamWaitEvent(0, evM[0], 0);
    cudaStreamWaitEvent(0, evM[1], 0);
    cudaStreamWaitEvent(0, evM[2], 0);
    pv_mma_kernel<<<dim3(8, 48), 256, PV_SMEM>>>(0);
    outproj_mma_kernel<<<dim3(8, 24), 256, OP_SMEM>>>(x, out, 0);

    // chain B on s2 (independent of chain A): pvB (bh 48..63) -> outprojB (b 3)
    cudaStreamWaitEvent(s2, evM[3], 0);
    pv_mma_kernel<<<dim3(8, 16), 256, PV_SMEM, s2>>>(48);
    outproj_mma_kernel<<<dim3(8, 8), 256, OP_SMEM, s2>>>(x, out, 3);
    cudaEventRecord(evB, s2);

    // join + LN
    cudaStreamWaitEvent(0, evB, 0);
    ln_kernel<<<4096, 256>>>(out, gamma, beta);
}

// round 15
// speedup vs baseline: 1.0866x; 1.0475x over previous
#include <cuda_runtime.h>
#include <cuda_fp16.h>
#include <math.h>
#include <stdint.h>

#define SEQ   1024
#define MEMN  1024
#define TT    2048
#define BATCH 4
#define NH    16
#define DH    64
#define DM    1024
#define BH    (BATCH*NH)   // 64

// ---------------- scratch (device globals, all fp16) ----------------
__device__ __half g_ac[(size_t)BH*SEQ*TT];
__device__ __half g_bd[(size_t)BH*SEQ*TT];

__device__ __half g_c [(size_t)8192*1024];
__device__ __half g_p [(size_t)8192*1024];
__device__ __half g_w [(size_t)4096*1024];
__device__ __half g_wo[(size_t)1024*1024];

__device__ __half g_qu[(size_t)BH*SEQ*DH];
__device__ __half g_qv[(size_t)BH*SEQ*DH];
__device__ __half g_k [(size_t)BH*TT*DH];
__device__ __half g_v [(size_t)BH*TT*DH];
__device__ __half g_r [(size_t)BH*TT*DH];

__device__ __half g_ph[(size_t)BH*SEQ*TT];
__device__ __half g_av[(size_t)SEQ*BATCH*DM];   // layout: [b][i][h*64+d]

// ---------------- helpers ----------------
__device__ __forceinline__ uint32_t smem_u32(const void* p){
    uint32_t a;
    asm("{ .reg .u64 t; cvta.to.shared.u64 t, %1; cvt.u32.u64 %0, t; }" : "=r"(a) : "l"(p));
    return a;
}
__device__ __forceinline__ void cp16(uint32_t s, const void* g){
    asm volatile("cp.async.cg.shared.global [%0], [%1], 16;" :: "r"(s), "l"(g));
}
#define CP_COMMIT() asm volatile("cp.async.commit_group;" ::: "memory")
#define CP_WAIT0()  asm volatile("cp.async.wait_group 0;" ::: "memory")

__device__ __forceinline__ void ldm4(uint32_t* r, uint32_t addr){
    asm volatile("ldmatrix.sync.aligned.m8n8.x4.shared.b16 {%0,%1,%2,%3}, [%4];"
        : "=r"(r[0]), "=r"(r[1]), "=r"(r[2]), "=r"(r[3]) : "r"(addr));
}
__device__ __forceinline__ void ldm4t(uint32_t* r, uint32_t addr){
    asm volatile("ldmatrix.sync.aligned.m8n8.x4.trans.shared.b16 {%0,%1,%2,%3}, [%4];"
        : "=r"(r[0]), "=r"(r[1]), "=r"(r[2]), "=r"(r[3]) : "r"(addr));
}
__device__ __forceinline__ void mma_f16(float* c, const uint32_t* a, uint32_t b0, uint32_t b1){
    asm volatile("mma.sync.aligned.m16n8k16.row.col.f32.f16.f16.f32 "
        "{%0,%1,%2,%3}, {%4,%5,%6,%7}, {%8,%9}, {%0,%1,%2,%3};"
        : "+f"(c[0]), "+f"(c[1]), "+f"(c[2]), "+f"(c[3])
        : "r"(a[0]), "r"(a[1]), "r"(a[2]), "r"(a[3]), "r"(b0), "r"(b1));
}
__device__ __forceinline__ uint4 pack8h(const float* v){
    __half2 a = __floats2half2_rn(v[0], v[1]);
    __half2 b = __floats2half2_rn(v[2], v[3]);
    __half2 c = __floats2half2_rn(v[4], v[5]);
    __half2 d = __floats2half2_rn(v[6], v[7]);
    uint4 r;
    r.x = *(uint32_t*)&a; r.y = *(uint32_t*)&b;
    r.z = *(uint32_t*)&c; r.w = *(uint32_t*)&d;
    return r;
}
__device__ __forceinline__ uint32_t packh2(float a, float b){
    __half2 h = __floats2half2_rn(a, b);
    return *(uint32_t*)&h;
}

__device__ __forceinline__ float warpReduceSum(float v){
    #pragma unroll
    for (int o = 16; o > 0; o >>= 1) v += __shfl_xor_sync(0xffffffffu, v, o);
    return v;
}

// ---------------- kernel 0: fp32 -> fp16 conversion ----------------
__global__ __launch_bounds__(256) void conv_kernel(
    const float* __restrict__ x, const float* __restrict__ mem,
    const float* __restrict__ pos, const float* __restrict__ Wqkv,
    const float* __restrict__ Wrel, const float* __restrict__ Wo)
{
    const size_t u = (size_t)blockIdx.x * 256 + threadIdx.x;
    const float* src;
    __half* dst;
    size_t elem;
    if (u < 2097152) {
        elem = u * 4;
        const size_t row = elem >> 10, col = elem & 1023;
        src = (row < 4096) ? (mem + row*1024 + col) : (x + (row-4096)*1024 + col);
        dst = g_c + elem;
    } else if (u < 4194304) {
        elem = (u - 2097152) * 4;
        src = pos + elem;
        dst = g_p + elem;
    } else if (u < 5242880) {
        elem = (u - 4194304) * 4;
        const size_t row = elem >> 10, col = elem & 1023;
        src = (row < 3072) ? (Wqkv + row*1024 + col) : (Wrel + (row-3072)*1024 + col);
        dst = g_w + elem;
    } else {
        elem = (u - 5242880) * 4;
        src = Wo + elem;
        dst = g_wo + elem;
    }
    float4 v = *(const float4*)src;
    __half2 h01 = __floats2half2_rn(v.x, v.y);
    __half2 h23 = __floats2half2_rn(v.z, v.w);
    *(uint2*)dst = make_uint2(*(uint32_t*)&h01, *(uint32_t*)&h23);
}

// ---------------- kernel 1: fp16 projection GEMM (K-chunk 64) ----------------
#define PJ_BUF   36864
#define PJ_SMEM  73728

__global__ __launch_bounds__(256) void proj_mma_kernel(
    const float* __restrict__ pbu, const float* __restrict__ pbv)
{
    extern __shared__ __align__(128) char smem[];
    const uint32_t sbase = smem_u32(smem);
    const int tid = threadIdx.x, lane = tid & 31, wid = tid >> 5;
    const int bid = blockIdx.x;
    int n0, m0;
    if (bid < 256){ n0 = (bid & 7) * 128; m0 = 4096 + (bid >> 3) * 128; }
    else { const int b2 = bid - 256; n0 = 1024 + (b2 % 24) * 128; m0 = (b2 / 24) * 128; }

    const bool is_rel = (n0 >= 3072);
    const __half* Ap = (is_rel ? g_p : g_c) + (size_t)m0 * 1024;
    const __half* Bp = g_w + (size_t)n0 * 1024;

    const int wm = (wid & 3) * 32;
    const int wn = (wid >> 2) * 64;
    const int lsel = lane & 15;
    const int kof  = (lane < 16) ? 0 : 8;

    float acc[2][8][4];
    #pragma unroll
    for (int mt = 0; mt < 2; mt++)
        #pragma unroll
        for (int nt = 0; nt < 8; nt++)
            #pragma unroll
            for (int q = 0; q < 4; q++) acc[mt][nt][q] = 0.f;

    auto issue = [&](int c, int b){
        const int k0 = c * 64;
        const uint32_t sb = sbase + b * PJ_BUF;
        #pragma unroll
        for (int p = 0; p < 4; p++){
            const int u = p * 256 + tid;
            const int row = u >> 3, seg = u & 7;
            const size_t go = (size_t)row * 1024 + k0 + seg * 8;
            const uint32_t so = row * 144 + seg * 16;
            cp16(sb + so,         Ap + go);
            cp16(sb + 18432 + so, Bp + go);
        }
        CP_COMMIT();
    };

    issue(0, 0);
    for (int c = 0; c < 16; c++){
        CP_WAIT0();
        __syncthreads();
        if (c + 1 < 16) issue(c + 1, (c + 1) & 1);
        const uint32_t sb = sbase + (c & 1) * PJ_BUF;
        #pragma unroll
        for (int kk = 0; kk < 64; kk += 16){
            uint32_t ah[2][4], bh[4][4];
            #pragma unroll
            for (int mt = 0; mt < 2; mt++)
                ldm4(ah[mt], sb + (wm + mt*16 + lsel) * 144 + (kk + kof) * 2);
            #pragma unroll
            for (int g = 0; g < 4; g++)
                ldm4(bh[g], sb + 18432 + (wn + g*16 + lsel) * 144 + (kk + kof) * 2);
            #pragma unroll
            for (int mt = 0; mt < 2; mt++)
                #pragma unroll
                for (int nt = 0; nt < 8; nt++){
                    const int g = nt >> 1, s = nt & 1;
                    mma_f16(acc[mt][nt], ah[mt], bh[g][s], bh[g][s+2]);
                }
        }
    }

    __syncthreads();
    float* stg = (float*)smem;
    const int fr = lane >> 2, fc = (lane & 3) * 2;
    #pragma unroll
    for (int mt = 0; mt < 2; mt++)
        #pragma unroll
        for (int nt = 0; nt < 8; nt++){
            const int col = wn + nt*8 + fc;
            const int row0 = wm + mt*16 + fr;
            stg[row0*132 + col]       = acc[mt][nt][0];
            stg[row0*132 + col + 1]   = acc[mt][nt][1];
            stg[(row0+8)*132 + col]   = acc[mt][nt][2];
            stg[(row0+8)*132 + col+1] = acc[mt][nt][3];
        }
    __syncthreads();

    const int rr = tid >> 1, hf = tid & 1;
    const int m = m0 + rr;
    const int t_ = m >> 2, b_ = m & 3;
    const float* src = stg + rr * 132 + hf * 64;
    const int nbase = n0 + hf * 64;
    const int cat = n0 >> 10;
    if (cat == 0){
        const int i = t_ - MEMN;
        const int h = nbase >> 6;
        const size_t off = (((size_t)(b_*NH + h))*SEQ + i)*DH;
        #pragma unroll
        for (int s = 0; s < 8; s++){
            float qu8[8], qv8[8];
            #pragma unroll
            for (int e = 0; e < 8; e++){
                const float v = src[s*8 + e];
                qu8[e] = v + pbu[nbase + s*8 + e];
                qv8[e] = v + pbv[nbase + s*8 + e];
            }
            *(uint4*)(g_qu + off + s*8) = pack8h(qu8);
            *(uint4*)(g_qv + off + s*8) = pack8h(qv8);
        }
    } else {
        const int nn = nbase - cat*1024;
        const int h = nn >> 6;
        __half* bptr = (cat == 1) ? g_k : (cat == 2) ? g_v : g_r;
        const size_t off = (((size_t)(b_*NH + h))*TT + t_)*DH;
        #pragma unroll
        for (int s = 0; s < 8; s++)
            *(uint4*)(bptr + off + s*8) = pack8h(src + s*8);
    }
}

// ---------------- kernel 2: fp16 score GEMMs, A-persistent 8-j-tile loop ----------------
#define SC_SMEM 90112

__global__ __launch_bounds__(256) void score_mma_kernel(int bh0)
{
    extern __shared__ __align__(128) char smem[];
    const uint32_t sbase = smem_u32(smem);
    const int tid = threadIdx.x, lane = tid & 31, wid = tid >> 5;
    const int z = blockIdx.z;
    const int bh = bh0 + (z >> 1), which = z & 1;
    const __half* Ap = (which ? g_qv : g_qu) + (size_t)bh * SEQ * DH;
    const __half* Bp = (which ? g_r  : g_k ) + (size_t)bh * TT  * DH;
    __half* Ob = (which ? g_bd : g_ac) + (size_t)bh * SEQ * TT;
    const int i0 = blockIdx.y * 128;
    const int jg = blockIdx.x * 8;

    const int wm = (wid & 3) * 32;
    const int wn = (wid >> 2) * 64;
    const int lsel = lane & 15;
    const int kof  = (lane < 16) ? 0 : 8;

    auto issueB = [&](int jt, int b){
        const int j0 = (jg + jt) * 128;
        const uint32_t sb = sbase + 18432 + b * 18432;
        #pragma unroll
        for (int p = 0; p < 4; p++){
            const int u = p * 256 + tid;
            const int row = u >> 3, seg = u & 7;
            cp16(sb + row * 144 + seg * 16, Bp + (size_t)(j0 + row) * DH + seg * 8);
        }
        CP_COMMIT();
    };

    {
        #pragma unroll
        for (int p = 0; p < 4; p++){
            const int u = p * 256 + tid;
            const int row = u >> 3, seg = u & 7;
            cp16(sbase + row * 144 + seg * 16, Ap + (size_t)(i0 + row) * DH + seg * 8);
        }
        issueB(0, 0);
    }

    __half* stg = (__half*)(smem + 55296);

    for (int jt = 0; jt < 8; jt++){
        float acc[2][8][4];
        #pragma unroll
        for (int mt = 0; mt < 2; mt++)
            #pragma unroll
            for (int nt = 0; nt < 8; nt++)
                #pragma unroll
                for (int q = 0; q < 4; q++) acc[mt][nt][q] = 0.f;

        CP_WAIT0();
        __syncthreads();
        if (jt + 1 < 8) issueB(jt + 1, (jt + 1) & 1);
        const uint32_t sbB = sbase + 18432 + (jt & 1) * 18432;

        #pragma unroll
        for (int kk = 0; kk < 64; kk += 16){
            uint32_t ah[2][4], bh[4][4];
            #pragma unroll
            for (int mt = 0; mt < 2; mt++)
                ldm4(ah[mt], sbase + (wm + mt*16 + lsel) * 144 + (kk + kof) * 2);
            #pragma unroll
            for (int g = 0; g < 4; g++)
                ldm4(bh[g], sbB + (wn + g*16 + lsel) * 144 + (kk + kof) * 2);
            #pragma unroll
            for (int mt = 0; mt < 2; mt++)
                #pragma unroll
                for (int nt = 0; nt < 8; nt++){
                    const int g = nt >> 1, s = nt & 1;
                    mma_f16(acc[mt][nt], ah[mt], bh[g][s], bh[g][s+2]);
                }
        }

        __syncthreads();
        const int fr = lane >> 2, fc = (lane & 3) * 2;
        #pragma unroll
        for (int mt = 0; mt < 2; mt++)
            #pragma unroll
            for (int nt = 0; nt < 8; nt++){
                const int col = wn + nt*8 + fc;
                const int row0 = wm + mt*16 + fr;
                *(uint32_t*)(stg + row0*136 + col)     = packh2(acc[mt][nt][0], acc[mt][nt][1]);
                *(uint32_t*)(stg + (row0+8)*136 + col) = packh2(acc[mt][nt][2], acc[mt][nt][3]);
            }
        __syncthreads();
        const int rr = tid >> 1, hf = tid & 1;
        const __half* srcp = stg + rr * 136 + hf * 64;
        __half* orow = Ob + (size_t)(i0 + rr) * TT + (jg + jt) * 128 + hf * 64;
        #pragma unroll
        for (int s = 0; s < 8; s++)
            *(uint4*)(orow + s*8) = *(const uint4*)(srcp + s*8);
        __syncthreads();
    }
}

// ---------------- kernel 3: rel-shift + softmax (no max; scores bounded) ----------------
__global__ __launch_bounds__(256) void softmax_shift_kernel(int bh0)
{
    const int i  = blockIdx.x;
    const int bh = bh0 + blockIdx.y;
    const int t  = threadIdx.x;
    const size_t rowoff = ((size_t)bh*SEQ + i) * TT;
    const __half* ac = g_ac + rowoff;
    const __half* bd0 = g_bd + rowoff;
    const __half* bd1 = bd0 + TT;

    float sv[8];
    float lsum = 0.f;
    #pragma unroll
    for (int q = 0; q < 8; q++){
        const int j = q*256 + t;
        const int delta = j - i;
        float bd;
        if (delta <= 1024)      bd = __half2float(bd0[delta + 1023]);
        else if (delta == 1025) bd = 0.f;
        else                    bd = __half2float(bd1[delta - 1026]);
        const float s = (__half2float(ac[j]) + bd) * 0.125f;
        const float p = __expf(s);
        sv[q] = p;
        lsum += p;
    }
    __shared__ float sh[8];
    float wsum = warpReduceSum(lsum);
    if ((t & 31) == 0) sh[t >> 5] = wsum;
    __syncthreads();
    float sum = 0.f;
    #pragma unroll
    for (int w = 0; w < 8; w++) sum += sh[w];
    const float sinv = 1.f / sum;

    __half* ph = g_ph + rowoff;
    #pragma unroll
    for (int q = 0; q < 8; q++){
        const int j = q*256 + t;
        ph[j] = __float2half_rn(sv[q] * sinv);
    }
}

// ---------------- kernel 4: fp16 PV GEMM (K-chunk 64), writes g_av[b][i][..] ----------------
#define PV_BUF   27648
#define PV_SMEM  55296

__global__ __launch_bounds__(256) void pv_mma_kernel(int bh0)
{
    extern __shared__ __align__(128) char smem[];
    const uint32_t sbase = smem_u32(smem);
    const int tid = threadIdx.x, lane = tid & 31, wid = tid >> 5;
    const int bh = bh0 + blockIdx.y;
    const int i0 = blockIdx.x * 128;
    const __half* Pp = g_ph + (size_t)bh*SEQ*TT + (size_t)i0*TT;
    const __half* Vp = g_v + (size_t)bh*TT*DH;

    const int wm = (wid & 3) * 32;
    const int wn = (wid >> 2) * 32;
    const int lsel = lane & 15;
    const int kof  = (lane < 16) ? 0 : 8;
    const int tcol = (lane >> 4) * 8;

    float acc[2][4][4];
    #pragma unroll
    for (int mt = 0; mt < 2; mt++)
        #pragma unroll
        for (int nt = 0; nt < 4; nt++)
            #pragma unroll
            for (int q = 0; q < 4; q++) acc[mt][nt][q] = 0.f;

    auto issue = [&](int c, int b){
        const int k0 = c * 64;
        const uint32_t sb = sbase + b * PV_BUF;
        #pragma unroll
        for (int p = 0; p < 4; p++){
            const int u = p * 256 + tid;
            const int row = u >> 3, seg = u & 7;
            cp16(sb + row * 144 + seg * 16, Pp + (size_t)row * TT + k0 + seg * 8);
        }
        #pragma unroll
        for (int p = 0; p < 2; p++){
            const int u = p * 256 + tid;
            const int row = u >> 3, seg = u & 7;
            cp16(sb + 18432 + row * 144 + seg * 16, Vp + (size_t)(k0 + row) * DH + seg * 8);
        }
        CP_COMMIT();
    };

    issue(0, 0);
    for (int c = 0; c < 32; c++){
        CP_WAIT0();
        __syncthreads();
        if (c + 1 < 32) issue(c + 1, (c + 1) & 1);
        const uint32_t sb = sbase + (c & 1) * PV_BUF;
        #pragma unroll
        for (int kk = 0; kk < 64; kk += 16){
            uint32_t ph[2][4], vh[2][4];
            #pragma unroll
            for (int mt = 0; mt < 2; mt++)
                ldm4(ph[mt], sb + (wm + mt*16 + lsel) * 144 + (kk + kof) * 2);
            #pragma unroll
            for (int g = 0; g < 2; g++)
                ldm4t(vh[g], sb + 18432 + (kk + lsel) * 144 + (wn + g*16 + tcol) * 2);
            #pragma unroll
            for (int mt = 0; mt < 2; mt++)
                #pragma unroll
                for (int nt = 0; nt < 4; nt++){
                    const int g = nt >> 1, s = nt & 1;
                    mma_f16(acc[mt][nt], ph[mt], vh[g][2*s], vh[g][2*s+1]);
                }
        }
    }

    __syncthreads();
    float* stg = (float*)smem;
    const int fr = lane >> 2, fc = (lane & 3) * 2;
    #pragma unroll
    for (int mt = 0; mt < 2; mt++)
        #pragma unroll
        for (int nt = 0; nt < 4; nt++){
            const int col = wn + nt*8 + fc;
            const int row0 = wm + mt*16 + fr;
            stg[row0*68 + col]       = acc[mt][nt][0];
            stg[row0*68 + col + 1]   = acc[mt][nt][1];
            stg[(row0+8)*68 + col]   = acc[mt][nt][2];
            stg[(row0+8)*68 + col+1] = acc[mt][nt][3];
        }
    __syncthreads();
    const int rr = tid >> 1, hf = tid & 1;
    const int b = bh >> 4, h = bh & 15;
    const int i = i0 + rr;
    const float* src = stg + rr * 68 + hf * 32;
    const size_t off = ((size_t)b*SEQ + i)*DM + h*DH + hf*32;   // [b][i][..]
    #pragma unroll
    for (int s = 0; s < 4; s++)
        *(uint4*)(g_av + off + s*8) = pack8h(src + s*8);
}

// ---------------- kernel 5: fp16 out projection + residual (batch range) ----------------
#define OP_BUF   36864
#define OP_SMEM  73728

__global__ __launch_bounds__(256) void outproj_mma_kernel(const float* __restrict__ x,
                                                          float* __restrict__ out, int b0)
{
    extern __shared__ __align__(128) char smem[];
    const uint32_t sbase = smem_u32(smem);
    const int tid = threadIdx.x, lane = tid & 31, wid = tid >> 5;
    const int n0 = blockIdx.x * 128;
    const int b  = b0 + (blockIdx.y >> 3);
    const int m0 = (blockIdx.y & 7) * 128;         // i-range within batch b
    const __half* Ap = g_av + ((size_t)b*SEQ + m0) * 1024;
    const __half* Bp = g_wo + (size_t)n0 * 1024;

    const int wm = (wid & 3) * 32;
    const int wn = (wid >> 2) * 64;
    const int lsel = lane & 15;
    const int kof  = (lane < 16) ? 0 : 8;

    float acc[2][8][4];
    #pragma unroll
    for (int mt = 0; mt < 2; mt++)
        #pragma unroll
        for (int nt = 0; nt < 8; nt++)
            #pragma unroll
            for (int q = 0; q < 4; q++) acc[mt][nt][q] = 0.f;

    auto issue = [&](int c, int bb){
        const int k0 = c * 64;
        const uint32_t sb = sbase + bb * OP_BUF;
        #pragma unroll
        for (int p = 0; p < 4; p++){
            const int u = p * 256 + tid;
            const int row = u >> 3, seg = u & 7;
            const size_t go = (size_t)row * 1024 + k0 + seg * 8;
            const uint32_t so = row * 144 + seg * 16;
            cp16(sb + so,         Ap + go);
            cp16(sb + 18432 + so, Bp + go);
        }
        CP_COMMIT();
    };

    issue(0, 0);
    for (int c = 0; c < 16; c++){
        CP_WAIT0();
        __syncthreads();
        if (c + 1 < 16) issue(c + 1, (c + 1) & 1);
        const uint32_t sb = sbase + (c & 1) * OP_BUF;
        #pragma unroll
        for (int kk = 0; kk < 64; kk += 16){
            uint32_t ah[2][4], bh[4][4];
            #pragma unroll
            for (int mt = 0; mt < 2; mt++)
                ldm4(ah[mt], sb + (wm + mt*16 + lsel) * 144 + (kk + kof) * 2);
            #pragma unroll
            for (int g = 0; g < 4; g++)
                ldm4(bh[g], sb + 18432 + (wn + g*16 + lsel) * 144 + (kk + kof) * 2);
            #pragma unroll
            for (int mt = 0; mt < 2; mt++)
                #pragma unroll
                for (int nt = 0; nt < 8; nt++){
                    const int g = nt >> 1, s = nt & 1;
                    mma_f16(acc[mt][nt], ah[mt], bh[g][s], bh[g][s+2]);
                }
        }
    }

    __syncthreads();
    float* stg = (float*)smem;
    const int fr = lane >> 2, fc = (lane & 3) * 2;
    #pragma unroll
    for (int mt = 0; mt < 2; mt++)
        #pragma unroll
        for (int nt = 0; nt < 8; nt++){
            const int col = wn + nt*8 + fc;
            const int row0 = wm + mt*16 + fr;
            stg[row0*132 + col]       = acc[mt][nt][0];
            stg[row0*132 + col + 1]   = acc[mt][nt][1];
            stg[(row0+8)*132 + col]   = acc[mt][nt][2];
            stg[(row0+8)*132 + col+1] = acc[mt][nt][3];
        }
    __syncthreads();
    const int rr = tid >> 1, hf = tid & 1;
    const int gm = (m0 + rr) * BATCH + b;          // global out row i*4+b
    const float* src = stg + rr * 132 + hf * 64;
    const float* xr = x + (size_t)gm*DM + n0 + hf*64;
    float* orow = out + (size_t)gm*DM + n0 + hf*64;
    #pragma unroll
    for (int s = 0; s < 16; s++){
        float4 v = *(const float4*)(src + s*4);
        float4 xx = *(const float4*)(xr + s*4);
        *(float4*)(orow + s*4) = make_float4(v.x+xx.x, v.y+xx.y, v.z+xx.z, v.w+xx.w);
    }
}

// ---------------- kernel 6: LayerNorm (all rows) ----------------
__global__ __launch_bounds__(256) void ln_kernel(float* __restrict__ out,
                                                 const float* __restrict__ gamma,
                                                 const float* __restrict__ beta)
{
    const int row = blockIdx.x;
    float* y = out + (size_t)row * DM;
    const int t = threadIdx.x;
    float v[4];
    float s = 0.f, sq = 0.f;
    #pragma unroll
    for (int q = 0; q < 4; q++){
        v[q] = y[q*256 + t];
        s += v[q];
        sq += v[q]*v[q];
    }
    __shared__ float sh[16];
    float ws = warpReduceSum(s);
    float wq = warpReduceSum(sq);
    if ((t & 31) == 0){ sh[t>>5] = ws; sh[8 + (t>>5)] = wq; }
    __syncthreads();
    s = 0.f; sq = 0.f;
    #pragma unroll
    for (int w = 0; w < 8; w++){ s += sh[w]; sq += sh[8+w]; }
    const float mu = s * (1.f/1024.f);
    const float var = sq * (1.f/1024.f) - mu*mu;
    const float rstd = rsqrtf(var + 1e-5f);
    #pragma unroll
    for (int q = 0; q < 4; q++){
        const int d = q*256 + t;
        y[d] = gamma[d] * ((v[q] - mu) * rstd) + beta[d];
    }
}

// ---------------- launch: 3-stream pipelined schedule (2 extra streams max) ----------------
#define NCHUNK 4
#define CHBH   16

extern "C" void kernel_launch(void* const* d_in, const int* in_sizes, int n_in,
                              void* d_out, int out_size)
{
    const float* x     = (const float*)d_in[0];
    const float* mem   = (const float*)d_in[1];
    const float* pos   = (const float*)d_in[2];
    const float* pbu   = (const float*)d_in[3];
    const float* pbv   = (const float*)d_in[4];
    const float* Wqkv  = (const float*)d_in[5];
    const float* Wrel  = (const float*)d_in[6];
    const float* Wo    = (const float*)d_in[7];
    const float* gamma = (const float*)d_in[8];
    const float* beta  = (const float*)d_in[9];
    float* out = (float*)d_out;

    static cudaStream_t s1 = nullptr, s2 = nullptr;
    static cudaEvent_t evPJ, evS[NCHUNK], evM[NCHUNK], evP[NCHUNK];
    if (!s1){
        cudaStreamCreateWithFlags(&s1, cudaStreamNonBlocking);
        cudaStreamCreateWithFlags(&s2, cudaStreamNonBlocking);
        cudaEventCreateWithFlags(&evPJ, cudaEventDisableTiming);
        for (int c = 0; c < NCHUNK; c++){
            cudaEventCreateWithFlags(&evS[c], cudaEventDisableTiming);
            cudaEventCreateWithFlags(&evM[c], cudaEventDisableTiming);
            cudaEventCreateWithFlags(&evP[c], cudaEventDisableTiming);
        }
        cudaFuncSetAttribute(proj_mma_kernel,    cudaFuncAttributeMaxDynamicSharedMemorySize, PJ_SMEM);
        cudaFuncSetAttribute(score_mma_kernel,   cudaFuncAttributeMaxDynamicSharedMemorySize, SC_SMEM);
        cudaFuncSetAttribute(pv_mma_kernel,      cudaFuncAttributeMaxDynamicSharedMemorySize, PV_SMEM);
        cudaFuncSetAttribute(outproj_mma_kernel, cudaFuncAttributeMaxDynamicSharedMemorySize, OP_SMEM);
    }

    conv_kernel<<<21504, 256>>>(x, mem, pos, Wqkv, Wrel, Wo);
    proj_mma_kernel<<<1792, 256, PJ_SMEM>>>(pbu, pbv);
    cudaEventRecord(evPJ, 0);
    cudaStreamWaitEvent(s2, evPJ, 0);

    // score chunks alternate streams 0/s2 (tail backfill); softmax on s1;
    // pv chunks alternate 0/s2 gated per-chunk on their own softmax event.
    for (int c = 0; c < NCHUNK; c++){
        cudaStream_t scs = (c & 1) ? s2 : 0;
        score_mma_kernel<<<dim3(2, 8, 2*CHBH), 256, SC_SMEM, scs>>>(c * CHBH);
        cudaEventRecord(evS[c], scs);
        cudaStreamWaitEvent(s1, evS[c], 0);
        softmax_shift_kernel<<<dim3(1024, CHBH), 256, 0, s1>>>(c * CHBH);
        cudaEventRecord(evM[c], s1);

        cudaStream_t pvs = (c & 1) ? s2 : 0;
        cudaStreamWaitEvent(pvs, evM[c], 0);
        pv_mma_kernel<<<dim3(8, CHBH), 256, PV_SMEM, pvs>>>(c * CHBH);
        cudaEventRecord(evP[c], pvs);
    }

    for (int c = 0; c < NCHUNK; c++)
        cudaStreamWaitEvent(0, evP[c], 0);
    outproj_mma_kernel<<<dim3(8, 32), 256, OP_SMEM>>>(x, out, 0);
    ln_kernel<<<4096, 256>>>(out, gamma, beta);
}

// round 17
// speedup vs baseline: 1.1380x; 1.0473x over previous
#include <cuda_runtime.h>
#include <cuda_fp16.h>
#include <math.h>
#include <stdint.h>

#define SEQ   1024
#define MEMN  1024
#define TT    2048
#define BATCH 4
#define NH    16
#define DH    64
#define DM    1024
#define BH    (BATCH*NH)   // 64

// ---------------- scratch (device globals, all fp16) ----------------
__device__ __half g_ac[(size_t)BH*SEQ*TT];
__device__ __half g_bd[(size_t)BH*SEQ*TT + 4096];   // +pad: softmax window reads past last row

__device__ __half g_c [(size_t)8192*1024];
__device__ __half g_p [(size_t)8192*1024];
__device__ __half g_w [(size_t)4096*1024];
__device__ __half g_wo[(size_t)1024*1024];

__device__ __half g_qu[(size_t)BH*SEQ*DH];
__device__ __half g_qv[(size_t)BH*SEQ*DH];
__device__ __half g_k [(size_t)BH*TT*DH];
__device__ __half g_v [(size_t)BH*TT*DH];
__device__ __half g_r [(size_t)BH*TT*DH];

__device__ __half g_ph[(size_t)BH*SEQ*TT];
__device__ __half g_av[(size_t)SEQ*BATCH*DM];   // layout: [b][i][h*64+d]

// ---------------- helpers ----------------
__device__ __forceinline__ uint32_t smem_u32(const void* p){
    uint32_t a;
    asm("{ .reg .u64 t; cvta.to.shared.u64 t, %1; cvt.u32.u64 %0, t; }" : "=r"(a) : "l"(p));
    return a;
}
__device__ __forceinline__ void cp16(uint32_t s, const void* g){
    asm volatile("cp.async.cg.shared.global [%0], [%1], 16;" :: "r"(s), "l"(g));
}
#define CP_COMMIT() asm volatile("cp.async.commit_group;" ::: "memory")
#define CP_WAIT0()  asm volatile("cp.async.wait_group 0;" ::: "memory")

__device__ __forceinline__ void ldm4(uint32_t* r, uint32_t addr){
    asm volatile("ldmatrix.sync.aligned.m8n8.x4.shared.b16 {%0,%1,%2,%3}, [%4];"
        : "=r"(r[0]), "=r"(r[1]), "=r"(r[2]), "=r"(r[3]) : "r"(addr));
}
__device__ __forceinline__ void ldm4t(uint32_t* r, uint32_t addr){
    asm volatile("ldmatrix.sync.aligned.m8n8.x4.trans.shared.b16 {%0,%1,%2,%3}, [%4];"
        : "=r"(r[0]), "=r"(r[1]), "=r"(r[2]), "=r"(r[3]) : "r"(addr));
}
__device__ __forceinline__ void mma_f16(float* c, const uint32_t* a, uint32_t b0, uint32_t b1){
    asm volatile("mma.sync.aligned.m16n8k16.row.col.f32.f16.f16.f32 "
        "{%0,%1,%2,%3}, {%4,%5,%6,%7}, {%8,%9}, {%0,%1,%2,%3};"
        : "+f"(c[0]), "+f"(c[1]), "+f"(c[2]), "+f"(c[3])
        : "r"(a[0]), "r"(a[1]), "r"(a[2]), "r"(a[3]), "r"(b0), "r"(b1));
}
__device__ __forceinline__ uint4 pack8h(const float* v){
    __half2 a = __floats2half2_rn(v[0], v[1]);
    __half2 b = __floats2half2_rn(v[2], v[3]);
    __half2 c = __floats2half2_rn(v[4], v[5]);
    __half2 d = __floats2half2_rn(v[6], v[7]);
    uint4 r;
    r.x = *(uint32_t*)&a; r.y = *(uint32_t*)&b;
    r.z = *(uint32_t*)&c; r.w = *(uint32_t*)&d;
    return r;
}
__device__ __forceinline__ uint32_t packh2(float a, float b){
    __half2 h = __floats2half2_rn(a, b);
    return *(uint32_t*)&h;
}
__device__ __forceinline__ uint32_t ex2h2(uint32_t in){
    uint32_t out;
    asm("ex2.approx.f16x2 %0, %1;" : "=r"(out) : "r"(in));
    return out;
}

__device__ __forceinline__ float warpReduceSum(float v){
    #pragma unroll
    for (int o = 16; o > 0; o >>= 1) v += __shfl_xor_sync(0xffffffffu, v, o);
    return v;
}

// ---------------- kernel 0: fp32 -> fp16 conversion ----------------
__global__ __launch_bounds__(256) void conv_kernel(
    const float* __restrict__ x, const float* __restrict__ mem,
    const float* __restrict__ pos, const float* __restrict__ Wqkv,
    const float* __restrict__ Wrel, const float* __restrict__ Wo)
{
    const size_t u = (size_t)blockIdx.x * 256 + threadIdx.x;
    const float* src;
    __half* dst;
    size_t elem;
    if (u < 2097152) {
        elem = u * 4;
        const size_t row = elem >> 10, col = elem & 1023;
        src = (row < 4096) ? (mem + row*1024 + col) : (x + (row-4096)*1024 + col);
        dst = g_c + elem;
    } else if (u < 4194304) {
        elem = (u - 2097152) * 4;
        src = pos + elem;
        dst = g_p + elem;
    } else if (u < 5242880) {
        elem = (u - 4194304) * 4;
        const size_t row = elem >> 10, col = elem & 1023;
        src = (row < 3072) ? (Wqkv + row*1024 + col) : (Wrel + (row-3072)*1024 + col);
        dst = g_w + elem;
    } else {
        elem = (u - 5242880) * 4;
        src = Wo + elem;
        dst = g_wo + elem;
    }
    float4 v = *(const float4*)src;
    __half2 h01 = __floats2half2_rn(v.x, v.y);
    __half2 h23 = __floats2half2_rn(v.z, v.w);
    *(uint2*)dst = make_uint2(*(uint32_t*)&h01, *(uint32_t*)&h23);
}

// ---------------- kernel 1: fp16 projection GEMM (per head-group chunk) ----------------
// chunk cg covers heads [4cg, 4cg+4): 448 blocks
//   bid < 64: q tiles (n0 = 256cg + {0,128}, m0 over x rows)
//   else: k/v/r tiles (n0 = cat*1024 + 256cg + {0,128}, m0 over all rows)
#define PJ_BUF   36864
#define PJ_SMEM  73728

__global__ __launch_bounds__(256) void proj_mma_kernel(
    const float* __restrict__ pbu, const float* __restrict__ pbv, int cg)
{
    extern __shared__ __align__(128) char smem[];
    const uint32_t sbase = smem_u32(smem);
    const int tid = threadIdx.x, lane = tid & 31, wid = tid >> 5;
    const int bid = blockIdx.x;
    int n0, m0;
    if (bid < 64){ n0 = 256*cg + (bid & 1)*128; m0 = 4096 + (bid >> 1)*128; }
    else {
        const int b2 = bid - 64;
        const int cat = 1 + b2/128;
        const int l = b2 % 128;
        n0 = cat*1024 + 256*cg + (l & 1)*128;
        m0 = (l >> 1) * 128;
    }

    const bool is_rel = (n0 >= 3072);
    const __half* Ap = (is_rel ? g_p : g_c) + (size_t)m0 * 1024;
    const __half* Bp = g_w + (size_t)n0 * 1024;

    const int wm = (wid & 3) * 32;
    const int wn = (wid >> 2) * 64;
    const int lsel = lane & 15;
    const int kof  = (lane < 16) ? 0 : 8;

    float acc[2][8][4];
    #pragma unroll
    for (int mt = 0; mt < 2; mt++)
        #pragma unroll
        for (int nt = 0; nt < 8; nt++)
            #pragma unroll
            for (int q = 0; q < 4; q++) acc[mt][nt][q] = 0.f;

    auto issue = [&](int c, int b){
        const int k0 = c * 64;
        const uint32_t sb = sbase + b * PJ_BUF;
        #pragma unroll
        for (int p = 0; p < 4; p++){
            const int u = p * 256 + tid;
            const int row = u >> 3, seg = u & 7;
            const size_t go = (size_t)row * 1024 + k0 + seg * 8;
            const uint32_t so = row * 144 + seg * 16;
            cp16(sb + so,         Ap + go);
            cp16(sb + 18432 + so, Bp + go);
        }
        CP_COMMIT();
    };

    issue(0, 0);
    for (int c = 0; c < 16; c++){
        CP_WAIT0();
        __syncthreads();
        if (c + 1 < 16) issue(c + 1, (c + 1) & 1);
        const uint32_t sb = sbase + (c & 1) * PJ_BUF;
        #pragma unroll
        for (int kk = 0; kk < 64; kk += 16){
            uint32_t ah[2][4], bh[4][4];
            #pragma unroll
            for (int mt = 0; mt < 2; mt++)
                ldm4(ah[mt], sb + (wm + mt*16 + lsel) * 144 + (kk + kof) * 2);
            #pragma unroll
            for (int g = 0; g < 4; g++)
                ldm4(bh[g], sb + 18432 + (wn + g*16 + lsel) * 144 + (kk + kof) * 2);
            #pragma unroll
            for (int mt = 0; mt < 2; mt++)
                #pragma unroll
                for (int nt = 0; nt < 8; nt++){
                    const int g = nt >> 1, s = nt & 1;
                    mma_f16(acc[mt][nt], ah[mt], bh[g][s], bh[g][s+2]);
                }
        }
    }

    __syncthreads();
    float* stg = (float*)smem;
    const int fr = lane >> 2, fc = (lane & 3) * 2;
    #pragma unroll
    for (int mt = 0; mt < 2; mt++)
        #pragma unroll
        for (int nt = 0; nt < 8; nt++){
            const int col = wn + nt*8 + fc;
            const int row0 = wm + mt*16 + fr;
            stg[row0*132 + col]       = acc[mt][nt][0];
            stg[row0*132 + col + 1]   = acc[mt][nt][1];
            stg[(row0+8)*132 + col]   = acc[mt][nt][2];
            stg[(row0+8)*132 + col+1] = acc[mt][nt][3];
        }
    __syncthreads();

    const int rr = tid >> 1, hf = tid & 1;
    const int m = m0 + rr;
    const int t_ = m >> 2, b_ = m & 3;
    const float* src = stg + rr * 132 + hf * 64;
    const int nbase = n0 + hf * 64;
    const int cat = n0 >> 10;
    if (cat == 0){
        const int i = t_ - MEMN;
        const int h = nbase >> 6;
        const size_t off = (((size_t)(b_*NH + h))*SEQ + i)*DH;
        #pragma unroll
        for (int s = 0; s < 8; s++){
            float qu8[8], qv8[8];
            #pragma unroll
            for (int e = 0; e < 8; e++){
                const float v = src[s*8 + e];
                qu8[e] = v + pbu[nbase + s*8 + e];
                qv8[e] = v + pbv[nbase + s*8 + e];
            }
            *(uint4*)(g_qu + off + s*8) = pack8h(qu8);
            *(uint4*)(g_qv + off + s*8) = pack8h(qv8);
        }
    } else {
        const int nn = nbase - cat*1024;
        const int h = nn >> 6;
        __half* bptr = (cat == 1) ? g_k : (cat == 2) ? g_v : g_r;
        const size_t off = (((size_t)(b_*NH + h))*TT + t_)*DH;
        #pragma unroll
        for (int s = 0; s < 8; s++)
            *(uint4*)(bptr + off + s*8) = pack8h(src + s*8);
    }
}

// ---------------- kernel 2: fp16 score GEMMs (head-group chunk) ----------------
#define SC_SMEM 90112

__global__ __launch_bounds__(256) void score_mma_kernel(int h0)
{
    extern __shared__ __align__(128) char smem[];
    const uint32_t sbase = smem_u32(smem);
    const int tid = threadIdx.x, lane = tid & 31, wid = tid >> 5;
    const int z = blockIdx.z;
    const int idx = z >> 1, which = z & 1;
    const int bh = (idx >> 2) * NH + h0 + (idx & 3);
    const __half* Ap = (which ? g_qv : g_qu) + (size_t)bh * SEQ * DH;
    const __half* Bp = (which ? g_r  : g_k ) + (size_t)bh * TT  * DH;
    __half* Ob = (which ? g_bd : g_ac) + (size_t)bh * SEQ * TT;
    const int i0 = blockIdx.y * 128;
    const int jg = blockIdx.x * 8;

    const int wm = (wid & 3) * 32;
    const int wn = (wid >> 2) * 64;
    const int lsel = lane & 15;
    const int kof  = (lane < 16) ? 0 : 8;

    auto issueB = [&](int jt, int b){
        const int j0 = (jg + jt) * 128;
        const uint32_t sb = sbase + 18432 + b * 18432;
        #pragma unroll
        for (int p = 0; p < 4; p++){
            const int u = p * 256 + tid;
            const int row = u >> 3, seg = u & 7;
            cp16(sb + row * 144 + seg * 16, Bp + (size_t)(j0 + row) * DH + seg * 8);
        }
        CP_COMMIT();
    };

    {
        #pragma unroll
        for (int p = 0; p < 4; p++){
            const int u = p * 256 + tid;
            const int row = u >> 3, seg = u & 7;
            cp16(sbase + row * 144 + seg * 16, Ap + (size_t)(i0 + row) * DH + seg * 8);
        }
        issueB(0, 0);
    }

    __half* stg = (__half*)(smem + 55296);

    for (int jt = 0; jt < 8; jt++){
        float acc[2][8][4];
        #pragma unroll
        for (int mt = 0; mt < 2; mt++)
            #pragma unroll
            for (int nt = 0; nt < 8; nt++)
                #pragma unroll
                for (int q = 0; q < 4; q++) acc[mt][nt][q] = 0.f;

        CP_WAIT0();
        __syncthreads();
        if (jt + 1 < 8) issueB(jt + 1, (jt + 1) & 1);
        const uint32_t sbB = sbase + 18432 + (jt & 1) * 18432;

        #pragma unroll
        for (int kk = 0; kk < 64; kk += 16){
            uint32_t ah[2][4], bh2[4][4];
            #pragma unroll
            for (int mt = 0; mt < 2; mt++)
                ldm4(ah[mt], sbase + (wm + mt*16 + lsel) * 144 + (kk + kof) * 2);
            #pragma unroll
            for (int g = 0; g < 4; g++)
                ldm4(bh2[g], sbB + (wn + g*16 + lsel) * 144 + (kk + kof) * 2);
            #pragma unroll
            for (int mt = 0; mt < 2; mt++)
                #pragma unroll
                for (int nt = 0; nt < 8; nt++){
                    const int g = nt >> 1, s = nt & 1;
                    mma_f16(acc[mt][nt], ah[mt], bh2[g][s], bh2[g][s+2]);
                }
        }

        __syncthreads();
        const int fr = lane >> 2, fc = (lane & 3) * 2;
        #pragma unroll
        for (int mt = 0; mt < 2; mt++)
            #pragma unroll
            for (int nt = 0; nt < 8; nt++){
                const int col = wn + nt*8 + fc;
                const int row0 = wm + mt*16 + fr;
                *(uint32_t*)(stg + row0*136 + col)     = packh2(acc[mt][nt][0], acc[mt][nt][1]);
                *(uint32_t*)(stg + (row0+8)*136 + col) = packh2(acc[mt][nt][2], acc[mt][nt][3]);
            }
        __syncthreads();
        const int rr = tid >> 1, hf = tid & 1;
        const __half* srcp = stg + rr * 136 + hf * 64;
        __half* orow = Ob + (size_t)(i0 + rr) * TT + (jg + jt) * 128 + hf * 64;
        #pragma unroll
        for (int s = 0; s < 8; s++)
            *(uint4*)(orow + s*8) = *(const uint4*)(srcp + s*8);
        __syncthreads();
    }
}

// ---------------- kernel 3: rel-shift + softmax via ex2.f16x2 ----------------
__global__ __launch_bounds__(256) void softmax_shift_kernel(int h0)
{
    const int i  = blockIdx.x;
    const int y  = blockIdx.y;
    const int bh = (y >> 2) * NH + h0 + (y & 3);
    const int t  = threadIdx.x;
    const size_t rowoff = ((size_t)bh*SEQ + i) * TT;
    const __half* ac = g_ac + rowoff;
    const __half* bd0 = g_bd + rowoff;
    const __half* bd1 = bd0 + TT;

    float sv[8];
    float lsum = 0.f;
    #pragma unroll
    for (int q = 0; q < 8; q += 2){
        float tt[2];
        #pragma unroll
        for (int e = 0; e < 2; e++){
            const int j = (q+e)*256 + t;
            const int delta = j - i;
            float bd;
            if (delta <= 1024)      bd = __half2float(bd0[delta + 1023]);
            else if (delta == 1025) bd = 0.f;
            else                    bd = __half2float(bd1[delta - 1026]);
            // p = exp((ac+bd)/8) = 2^((ac+bd)*0.125*log2(e))
            tt[e] = (__half2float(ac[j]) + bd) * 0.18033688f;
        }
        const uint32_t ph2 = ex2h2(packh2(tt[0], tt[1]));
        const __half2 hp = *(const __half2*)&ph2;
        const float2 fp = __half22float2(hp);
        sv[q] = fp.x; sv[q+1] = fp.y;
        lsum += fp.x + fp.y;
    }
    __shared__ float sh[8];
    float wsum = warpReduceSum(lsum);
    if ((t & 31) == 0) sh[t >> 5] = wsum;
    __syncthreads();
    float sum = 0.f;
    #pragma unroll
    for (int w = 0; w < 8; w++) sum += sh[w];
    const float sinv = 1.f / sum;

    __half* ph = g_ph + rowoff;
    #pragma unroll
    for (int q = 0; q < 8; q++){
        const int j = q*256 + t;
        ph[j] = __float2half_rn(sv[q] * sinv);
    }
}

// ---------------- kernel 4: fp16 PV GEMM (head-group chunk) ----------------
#define PV_BUF   27648
#define PV_SMEM  55296

__global__ __launch_bounds__(256) void pv_mma_kernel(int h0)
{
    extern __shared__ __align__(128) char smem[];
    const uint32_t sbase = smem_u32(smem);
    const int tid = threadIdx.x, lane = tid & 31, wid = tid >> 5;
    const int y = blockIdx.y;
    const int bh = (y >> 2) * NH + h0 + (y & 3);
    const int i0 = blockIdx.x * 128;
    const __half* Pp = g_ph + (size_t)bh*SEQ*TT + (size_t)i0*TT;
    const __half* Vp = g_v + (size_t)bh*TT*DH;

    const int wm = (wid & 3) * 32;
    const int wn = (wid >> 2) * 32;
    const int lsel = lane & 15;
    const int kof  = (lane < 16) ? 0 : 8;
    const int tcol = (lane >> 4) * 8;

    float acc[2][4][4];
    #pragma unroll
    for (int mt = 0; mt < 2; mt++)
        #pragma unroll
        for (int nt = 0; nt < 4; nt++)
            #pragma unroll
            for (int q = 0; q < 4; q++) acc[mt][nt][q] = 0.f;

    auto issue = [&](int c, int b){
        const int k0 = c * 64;
        const uint32_t sb = sbase + b * PV_BUF;
        #pragma unroll
        for (int p = 0; p < 4; p++){
            const int u = p * 256 + tid;
            const int row = u >> 3, seg = u & 7;
            cp16(sb + row * 144 + seg * 16, Pp + (size_t)row * TT + k0 + seg * 8);
        }
        #pragma unroll
        for (int p = 0; p < 2; p++){
            const int u = p * 256 + tid;
            const int row = u >> 3, seg = u & 7;
            cp16(sb + 18432 + row * 144 + seg * 16, Vp + (size_t)(k0 + row) * DH + seg * 8);
        }
        CP_COMMIT();
    };

    issue(0, 0);
    for (int c = 0; c < 32; c++){
        CP_WAIT0();
        __syncthreads();
        if (c + 1 < 32) issue(c + 1, (c + 1) & 1);
        const uint32_t sb = sbase + (c & 1) * PV_BUF;
        #pragma unroll
        for (int kk = 0; kk < 64; kk += 16){
            uint32_t ph[2][4], vh[2][4];
            #pragma unroll
            for (int mt = 0; mt < 2; mt++)
                ldm4(ph[mt], sb + (wm + mt*16 + lsel) * 144 + (kk + kof) * 2);
            #pragma unroll
            for (int g = 0; g < 2; g++)
                ldm4t(vh[g], sb + 18432 + (kk + lsel) * 144 + (wn + g*16 + tcol) * 2);
            #pragma unroll
            for (int mt = 0; mt < 2; mt++)
                #pragma unroll
                for (int nt = 0; nt < 4; nt++){
                    const int g = nt >> 1, s = nt & 1;
                    mma_f16(acc[mt][nt], ph[mt], vh[g][2*s], vh[g][2*s+1]);
                }
        }
    }

    __syncthreads();
    float* stg = (float*)smem;
    const int fr = lane >> 2, fc = (lane & 3) * 2;
    #pragma unroll
    for (int mt = 0; mt < 2; mt++)
        #pragma unroll
        for (int nt = 0; nt < 4; nt++){
            const int col = wn + nt*8 + fc;
            const int row0 = wm + mt*16 + fr;
            stg[row0*68 + col]       = acc[mt][nt][0];
            stg[row0*68 + col + 1]   = acc[mt][nt][1];
            stg[(row0+8)*68 + col]   = acc[mt][nt][2];
            stg[(row0+8)*68 + col+1] = acc[mt][nt][3];
        }
    __syncthreads();
    const int rr = tid >> 1, hf = tid & 1;
    const int b = bh >> 4, h = bh & 15;
    const int i = i0 + rr;
    const float* src = stg + rr * 68 + hf * 32;
    const size_t off = ((size_t)b*SEQ + i)*DM + h*DH + hf*32;   // [b][i][..]
    #pragma unroll
    for (int s = 0; s < 4; s++)
        *(uint4*)(g_av + off + s*8) = pack8h(src + s*8);
}

// ---------------- kernel 5: fp16 out projection + residual ----------------
#define OP_BUF   36864
#define OP_SMEM  73728

__global__ __launch_bounds__(256) void outproj_mma_kernel(const float* __restrict__ x,
                                                          float* __restrict__ out)
{
    extern __shared__ __align__(128) char smem[];
    const uint32_t sbase = smem_u32(smem);
    const int tid = threadIdx.x, lane = tid & 31, wid = tid >> 5;
    const int n0 = blockIdx.x * 128;
    const int b  = blockIdx.y >> 3;
    const int m0 = (blockIdx.y & 7) * 128;
    const __half* Ap = g_av + ((size_t)b*SEQ + m0) * 1024;
    const __half* Bp = g_wo + (size_t)n0 * 1024;

    const int wm = (wid & 3) * 32;
    const int wn = (wid >> 2) * 64;
    const int lsel = lane & 15;
    const int kof  = (lane < 16) ? 0 : 8;

    float acc[2][8][4];
    #pragma unroll
    for (int mt = 0; mt < 2; mt++)
        #pragma unroll
        for (int nt = 0; nt < 8; nt++)
            #pragma unroll
            for (int q = 0; q < 4; q++) acc[mt][nt][q] = 0.f;

    auto issue = [&](int c, int bb){
        const int k0 = c * 64;
        const uint32_t sb = sbase + bb * OP_BUF;
        #pragma unroll
        for (int p = 0; p < 4; p++){
            const int u = p * 256 + tid;
            const int row = u >> 3, seg = u & 7;
            const size_t go = (size_t)row * 1024 + k0 + seg * 8;
            const uint32_t so = row * 144 + seg * 16;
            cp16(sb + so,         Ap + go);
            cp16(sb + 18432 + so, Bp + go);
        }
        CP_COMMIT();
    };

    issue(0, 0);
    for (int c = 0; c < 16; c++){
        CP_WAIT0();
        __syncthreads();
        if (c + 1 < 16) issue(c + 1, (c + 1) & 1);
        const uint32_t sb = sbase + (c & 1) * OP_BUF;
        #pragma unroll
        for (int kk = 0; kk < 64; kk += 16){
            uint32_t ah[2][4], bh[4][4];
            #pragma unroll
            for (int mt = 0; mt < 2; mt++)
                ldm4(ah[mt], sb + (wm + mt*16 + lsel) * 144 + (kk + kof) * 2);
            #pragma unroll
            for (int g = 0; g < 4; g++)
                ldm4(bh[g], sb + 18432 + (wn + g*16 + lsel) * 144 + (kk + kof) * 2);
            #pragma unroll
            for (int mt = 0; mt < 2; mt++)
                #pragma unroll
                for (int nt = 0; nt < 8; nt++){
                    const int g = nt >> 1, s = nt & 1;
                    mma_f16(acc[mt][nt], ah[mt], bh[g][s], bh[g][s+2]);
                }
        }
    }

    __syncthreads();
    float* stg = (float*)smem;
    const int fr = lane >> 2, fc = (lane & 3) * 2;
    #pragma unroll
    for (int mt = 0; mt < 2; mt++)
        #pragma unroll
        for (int nt = 0; nt < 8; nt++){
            const int col = wn + nt*8 + fc;
            const int row0 = wm + mt*16 + fr;
            stg[row0*132 + col]       = acc[mt][nt][0];
            stg[row0*132 + col + 1]   = acc[mt][nt][1];
            stg[(row0+8)*132 + col]   = acc[mt][nt][2];
            stg[(row0+8)*132 + col+1] = acc[mt][nt][3];
        }
    __syncthreads();
    const int rr = tid >> 1, hf = tid & 1;
    const int gm = (m0 + rr) * BATCH + b;
    const float* src = stg + rr * 132 + hf * 64;
    const float* xr = x + (size_t)gm*DM + n0 + hf*64;
    float* orow = out + (size_t)gm*DM + n0 + hf*64;
    #pragma unroll
    for (int s = 0; s < 16; s++){
        float4 v = *(const float4*)(src + s*4);
        float4 xx = *(const float4*)(xr + s*4);
        *(float4*)(orow + s*4) = make_float4(v.x+xx.x, v.y+xx.y, v.z+xx.z, v.w+xx.w);
    }
}

// ---------------- kernel 6: LayerNorm ----------------
__global__ __launch_bounds__(256) void ln_kernel(float* __restrict__ out,
                                                 const float* __restrict__ gamma,
                                                 const float* __restrict__ beta)
{
    const int row = blockIdx.x;
    float* y = out + (size_t)row * DM;
    const int t = threadIdx.x;
    float v[4];
    float s = 0.f, sq = 0.f;
    #pragma unroll
    for (int q = 0; q < 4; q++){
        v[q] = y[q*256 + t];
        s += v[q];
        sq += v[q]*v[q];
    }
    __shared__ float sh[16];
    float ws = warpReduceSum(s);
    float wq = warpReduceSum(sq);
    if ((t & 31) == 0){ sh[t>>5] = ws; sh[8 + (t>>5)] = wq; }
    __syncthreads();
    s = 0.f; sq = 0.f;
    #pragma unroll
    for (int w = 0; w < 8; w++){ s += sh[w]; sq += sh[8+w]; }
    const float mu = s * (1.f/1024.f);
    const float var = sq * (1.f/1024.f) - mu*mu;
    const float rstd = rsqrtf(var + 1e-5f);
    #pragma unroll
    for (int q = 0; q < 4; q++){
        const int d = q*256 + t;
        y[d] = gamma[d] * ((v[q] - mu) * rstd) + beta[d];
    }
}

// ---------------- launch: head-group pipelined schedule (2 extra streams) ----------------
#define NCHUNK 4

extern "C" void kernel_launch(void* const* d_in, const int* in_sizes, int n_in,
                              void* d_out, int out_size)
{
    const float* x     = (const float*)d_in[0];
    const float* mem   = (const float*)d_in[1];
    const float* pos   = (const float*)d_in[2];
    const float* pbu   = (const float*)d_in[3];
    const float* pbv   = (const float*)d_in[4];
    const float* Wqkv  = (const float*)d_in[5];
    const float* Wrel  = (const float*)d_in[6];
    const float* Wo    = (const float*)d_in[7];
    const float* gamma = (const float*)d_in[8];
    const float* beta  = (const float*)d_in[9];
    float* out = (float*)d_out;

    static cudaStream_t s1 = nullptr, s2 = nullptr;
    static cudaEvent_t evC, evS[NCHUNK], evM[NCHUNK], evP[NCHUNK];
    if (!s1){
        cudaStreamCreateWithFlags(&s1, cudaStreamNonBlocking);
        cudaStreamCreateWithFlags(&s2, cudaStreamNonBlocking);
        cudaEventCreateWithFlags(&evC, cudaEventDisableTiming);
        for (int c = 0; c < NCHUNK; c++){
            cudaEventCreateWithFlags(&evS[c], cudaEventDisableTiming);
            cudaEventCreateWithFlags(&evM[c], cudaEventDisableTiming);
            cudaEventCreateWithFlags(&evP[c], cudaEventDisableTiming);
        }
        cudaFuncSetAttribute(proj_mma_kernel,    cudaFuncAttributeMaxDynamicSharedMemorySize, PJ_SMEM);
        cudaFuncSetAttribute(score_mma_kernel,   cudaFuncAttributeMaxDynamicSharedMemorySize, SC_SMEM);
        cudaFuncSetAttribute(pv_mma_kernel,      cudaFuncAttributeMaxDynamicSharedMemorySize, PV_SMEM);
        cudaFuncSetAttribute(outproj_mma_kernel, cudaFuncAttributeMaxDynamicSharedMemorySize, OP_SMEM);
    }

    conv_kernel<<<21504, 256>>>(x, mem, pos, Wqkv, Wrel, Wo);
    cudaEventRecord(evC, 0);
    cudaStreamWaitEvent(s2, evC, 0);

    // pipeline: per head-group chunk c (heads 4c..4c+3):
    //   proj_c -> score_c on alternating stream (0/s2); softmax_c on s1; pv_c on opposite stream
    for (int c = 0; c < NCHUNK; c++){
        cudaStream_t scs = (c & 1) ? s2 : 0;
        proj_mma_kernel<<<448, 256, PJ_SMEM, scs>>>(pbu, pbv, c);
        score_mma_kernel<<<dim3(2, 8, 32), 256, SC_SMEM, scs>>>(4*c);
        cudaEventRecord(evS[c], scs);
        cudaStreamWaitEvent(s1, evS[c], 0);
        softmax_shift_kernel<<<dim3(1024, 16), 256, 0, s1>>>(4*c);
        cudaEventRecord(evM[c], s1);
    }
    for (int c = 0; c < NCHUNK; c++){
        cudaStream_t pvs = (c & 1) ? 0 : s2;      // opposite of producer
        cudaStreamWaitEvent(pvs, evM[c], 0);
        pv_mma_kernel<<<dim3(8, 16), 256, PV_SMEM, pvs>>>(4*c);
        cudaEventRecord(evP[c], pvs);
    }

    for (int c = 0; c < NCHUNK; c++)
        cudaStreamWaitEvent(0, evP[c], 0);
    outproj_mma_kernel<<<dim3(8, 32), 256, OP_SMEM>>>(x, out);
    ln_kernel<<<4096, 256>>>(out, gamma, beta);
}